// round 9
// baseline (speedup 1.0000x reference)
#include <cuda_runtime.h>

// Problem constants (fixed by the dataset): N=30000, C=3, D=128, K=10, H=64
#define DD   128
#define HH   64
#define GATE 256   // 4*H per direction
#define ROW  512   // both directions of gate pre-activations

#define NMAX 30000

// Scratch (static device globals — allocation-free rule)
__device__ __align__(16) float g_gxbuf[(size_t)NMAX * 3 * ROW];   // content gate preacts (reused per s)
__device__ __align__(16) float g_gxn[(size_t)3 * NMAX * ROW];     // neighbor gate preacts per s
__device__ __align__(16) float g_content[(size_t)3 * NMAX * DD];  // content embeddings
__device__ __align__(16) float g_neigh[(size_t)9 * NMAX * DD];    // neigh[d][s][n][128]

__device__ __forceinline__ float sigm(float x) { return 1.f / (1.f + __expf(-x)); }
__device__ __forceinline__ float tanh_(float x) { return 2.f / (1.f + __expf(-2.f * x)) - 1.f; }

// ---- packed f32x2 (Blackwell FFMA2) helpers ----
typedef unsigned long long u64t;

__device__ __forceinline__ void ffma2(u64t& d, u64t a, u64t b) {
    asm("fma.rn.f32x2 %0, %1, %2, %0;" : "+l"(d) : "l"(a), "l"(b));
}
__device__ __forceinline__ u64t pk2(float lo, float hi) {
    u64t r; asm("mov.b64 %0, {%1, %2};" : "=l"(r) : "f"(lo), "f"(hi)); return r;
}
__device__ __forceinline__ void upk2(u64t v, float& lo, float& hi) {
    asm("mov.b64 {%0, %1}, %2;" : "=f"(lo), "=f"(hi) : "l"(v));
}

// ---------------------------------------------------------------------------
// GEMM: C[m][j] = sum_k A[m][k] * W[j][k] + b1[j] + b2[j]
// A: [M,128] row-major, W: [512,128] row-major, C: [M,512]
// grid: (ceil(M/64), 4)  block: 256.  Inner loop uses FFMA2 (f32x2).
// ---------------------------------------------------------------------------
#define GEMM_SMEM ((128 * 68 + 128 * 132) * 4)

__global__ __launch_bounds__(256) void gemm_bias(
    const float* __restrict__ A, const float* __restrict__ W,
    const float* __restrict__ b1, const float* __restrict__ b2,
    float* __restrict__ C, int M)
{
    extern __shared__ float sm[];
    float* Ast = sm;              // [128 k][68 m]
    float* Wst = sm + 128 * 68;   // [128 k][132 j]
    const int tid = threadIdx.x;
    const int bm = blockIdx.x, jc = blockIdx.y;

    for (int q = tid; q < 64 * 32; q += 256) {
        int r = q >> 5;
        int k4 = (q & 31) << 2;
        int gm = bm * 64 + r;
        float4 v = make_float4(0.f, 0.f, 0.f, 0.f);
        if (gm < M) v = *(const float4*)(A + (size_t)gm * 128 + k4);
        Ast[(k4 + 0) * 68 + r] = v.x;
        Ast[(k4 + 1) * 68 + r] = v.y;
        Ast[(k4 + 2) * 68 + r] = v.z;
        Ast[(k4 + 3) * 68 + r] = v.w;
    }
    for (int q = tid; q < 128 * 32; q += 256) {
        int jj = q >> 5;
        int k4 = (q & 31) << 2;
        float4 v = *(const float4*)(W + ((size_t)(jc * 128 + jj)) * 128 + k4);
        Wst[(k4 + 0) * 132 + jj] = v.x;
        Wst[(k4 + 1) * 132 + jj] = v.y;
        Wst[(k4 + 2) * 132 + jj] = v.z;
        Wst[(k4 + 3) * 132 + jj] = v.w;
    }
    __syncthreads();

    const int tx = tid & 15;   // j group: 8 cols (4 packed pairs)
    const int ty = tid >> 4;   // m group: 4 rows
    u64t acc2[4][4];
#pragma unroll
    for (int i = 0; i < 4; i++)
#pragma unroll
        for (int j = 0; j < 4; j++) acc2[i][j] = pk2(0.f, 0.f);

#pragma unroll 4
    for (int kk = 0; kk < 128; kk++) {
        float4 a = *(const float4*)(Ast + kk * 68 + (ty << 2));
        // W cols as ready-made packed pairs (16B-aligned: pitch 132, tx*8 floats)
        ulonglong2 wp0 = *(const ulonglong2*)(Wst + kk * 132 + (tx << 3));
        ulonglong2 wp1 = *(const ulonglong2*)(Wst + kk * 132 + (tx << 3) + 4);
        u64t wv[4] = {wp0.x, wp0.y, wp1.x, wp1.y};
        u64t am[4] = {pk2(a.x, a.x), pk2(a.y, a.y), pk2(a.z, a.z), pk2(a.w, a.w)};
#pragma unroll
        for (int mi = 0; mi < 4; mi++)
#pragma unroll
            for (int jp = 0; jp < 4; jp++) ffma2(acc2[mi][jp], am[mi], wv[jp]);
    }

    const int jb = (jc << 7) + (tx << 3);
    float bb[8];
#pragma unroll
    for (int ji = 0; ji < 8; ji++) bb[ji] = b1[jb + ji] + b2[jb + ji];

#pragma unroll
    for (int mi = 0; mi < 4; mi++) {
        int gm = (bm << 6) + (ty << 2) + mi;
        if (gm < M) {
            float o[8];
#pragma unroll
            for (int jp = 0; jp < 4; jp++) upk2(acc2[mi][jp], o[2 * jp], o[2 * jp + 1]);
            float4 o0 = make_float4(o[0] + bb[0], o[1] + bb[1], o[2] + bb[2], o[3] + bb[3]);
            float4 o1 = make_float4(o[4] + bb[4], o[5] + bb[5], o[6] + bb[6], o[7] + bb[7]);
            *(float4*)(C + (size_t)gm * ROW + jb)     = o0;
            *(float4*)(C + (size_t)gm * ROW + jb + 4) = o1;
        }
    }
}

// ---------------------------------------------------------------------------
// Bi-LSTM recurrence, v3: 8x8 thread tile with packed FFMA2 inner loop.
// CTA: 64 nodes x 256 gate-cols, 256 threads, 2 CTAs/SM.
//   ng = tid>>5 -> nodes mbase..mbase+7 (whole warp shares ng: H reads broadcast)
//   kg = tid&31 -> hidden-unit pair u0=2kg, u0+1; cols {g*64+u0, g*64+u0+1}.
// Accumulators acc2[g][i] pack (u0,u1): gx loads and Whh cols are natural
// 64-bit pairs; H is stored DUPLICATED in SMEM so (h,h) pairs load directly.
// Per kk per thread: 4 LDS.128 + 4 LDS.64 + 32 FFMA2 = 40 instr / 64 FMAs.
// Single H buffer, two barriers per step.
// grid: (ceil(N/64), 2, pairs). idx==null -> content mode (row = n*K + t).
// ---------------------------------------------------------------------------
#define HP2 132   // Hdup pitch in floats (row = 64 nodes * 2 dup + pad; 16B-aligned)
#define RSMEM ((64 * 260 + 64 * HP2) * 4 + 64 * 10 * 4)

__global__ __launch_bounds__(256, 2) void bilstm_recur(
    const float* __restrict__ gx, const int* __restrict__ idx,
    const float* __restrict__ Whh, float* __restrict__ out,
    int N, int K)
{
    extern __shared__ float sm[];
    float* WhhT = sm;                          // [64 k][260 j-pitch]
    float* Hdup = sm + 64 * 260;               // [64 u][HP2]: (h,h) pairs per node
    int*   ids  = (int*)(Hdup + 64 * HP2);     // [64 m][K]

    const int tid = threadIdx.x;
    const int dir = blockIdx.y;

    if (idx) {
        int p = blockIdx.z;
        int d = p / 3, s = p - d * 3;
        gx  += (size_t)s * N * ROW;
        idx += (size_t)(s * 3 + d) * N * K;
        Whh += (size_t)s * 2 * GATE * HH;
        out += (size_t)(d * 3 + s) * N * DD;
    }
    Whh += (size_t)dir * GATE * HH;
    const int node0 = blockIdx.x * 64;

    // Whh[j][k] -> WhhT[k][j]
    for (int i = tid; i < GATE * HH; i += 256) {
        int j = i >> 6, k = i & 63;
        WhhT[k * 260 + j] = Whh[i];
    }
    for (int i = tid; i < 64 * HP2; i += 256) Hdup[i] = 0.f;
    if (idx) {
        for (int i = tid; i < 64 * K; i += 256) {
            int m = i / K;
            int n = node0 + m;
            ids[i] = (n < N) ? idx[(size_t)n * K + (i - m * K)] : 0;
        }
    }
    __syncthreads();

    const int ng = tid >> 5;
    const int kg = tid & 31;
    const int u0 = kg << 1;
    const int mbase = ng << 3;

    float c0[8], c1[8], hs0[8], hs1[8];
#pragma unroll
    for (int i = 0; i < 8; i++) { c0[i] = 0.f; c1[i] = 0.f; hs0[i] = 0.f; hs1[i] = 0.f; }

    const float* gbase = gx + dir * GATE + u0;

    for (int t = 0; t < K; t++) {
        const int tt = dir ? (K - 1 - t) : t;

        // Load gate pre-activations directly as packed (u0,u1) accumulators.
        u64t acc2[4][8];
#pragma unroll
        for (int i = 0; i < 8; i++) {
            int m = mbase + i;
            size_t row;
            if (idx) {
                row = (size_t)ids[m * K + tt];
            } else {
                int n = node0 + m;
                row = (size_t)(n < N ? n : 0) * K + tt;
            }
            const float* pr = gbase + row * ROW;
#pragma unroll
            for (int g = 0; g < 4; g++)
                acc2[g][i] = *(const u64t*)(pr + (g << 6));
        }

        // acc2 += H(prev) @ Whh^T  — packed FFMA2, H pairs pre-duplicated.
#pragma unroll 2
        for (int kk = 0; kk < 64; kk++) {
            const float* hrow = Hdup + kk * HP2 + (mbase << 1);
            ulonglong2 h01 = *(const ulonglong2*)(hrow);
            ulonglong2 h23 = *(const ulonglong2*)(hrow + 4);
            ulonglong2 h45 = *(const ulonglong2*)(hrow + 8);
            ulonglong2 h67 = *(const ulonglong2*)(hrow + 12);
            u64t hp[8] = {h01.x, h01.y, h23.x, h23.y, h45.x, h45.y, h67.x, h67.y};
            const float* wr = WhhT + kk * 260 + u0;
            u64t w0 = *(const u64t*)(wr);
            u64t w1 = *(const u64t*)(wr + 64);
            u64t w2 = *(const u64t*)(wr + 128);
            u64t w3 = *(const u64t*)(wr + 192);
#pragma unroll
            for (int i = 0; i < 8; i++) {
                ffma2(acc2[0][i], hp[i], w0);
                ffma2(acc2[1][i], hp[i], w1);
                ffma2(acc2[2][i], hp[i], w2);
                ffma2(acc2[3][i], hp[i], w3);
            }
        }
        __syncthreads();   // all reads of H(t-1) done before overwrite

        // Gate math + write new H (duplicated pairs) for both hidden units.
        float hv0[8], hv1[8];
#pragma unroll
        for (int i = 0; i < 8; i++) {
            float i0, i1, f0, f1, g0, g1, o0, o1;
            upk2(acc2[0][i], i0, i1);
            upk2(acc2[1][i], f0, f1);
            upk2(acc2[2][i], g0, g1);
            upk2(acc2[3][i], o0, o1);
            c0[i] = sigm(f0) * c0[i] + sigm(i0) * tanh_(g0);
            hv0[i] = sigm(o0) * tanh_(c0[i]);
            hs0[i] += hv0[i];
            c1[i] = sigm(f1) * c1[i] + sigm(i1) * tanh_(g1);
            hv1[i] = sigm(o1) * tanh_(c1[i]);
            hs1[i] += hv1[i];
        }
        {
            float* w0p = Hdup + u0 * HP2 + (mbase << 1);
            float* w1p = Hdup + (u0 + 1) * HP2 + (mbase << 1);
#pragma unroll
            for (int p = 0; p < 4; p++) {
                *(float4*)(w0p + 4 * p) =
                    make_float4(hv0[2 * p], hv0[2 * p], hv0[2 * p + 1], hv0[2 * p + 1]);
                *(float4*)(w1p + 4 * p) =
                    make_float4(hv1[2 * p], hv1[2 * p], hv1[2 * p + 1], hv1[2 * p + 1]);
            }
        }
        __syncthreads();   // new H visible before next step
    }

    const float inv = 1.f / (float)K;
#pragma unroll
    for (int i = 0; i < 8; i++) {
        int n = node0 + mbase + i;
        if (n < N) {
            *(float2*)(out + (size_t)n * DD + dir * HH + u0) =
                make_float2(hs0[i] * inv, hs1[i] * inv);
        }
    }
}

// ---------------------------------------------------------------------------
// Attention fusion: one warp per (d, n).
// ---------------------------------------------------------------------------
__global__ void attn_fuse(const float* __restrict__ content,
                          const float* __restrict__ neigh,
                          const float* __restrict__ attn_w,
                          const float* __restrict__ attn_b,
                          float* __restrict__ out, int N)
{
    int w = (blockIdx.x * blockDim.x + threadIdx.x) >> 5;
    if (w >= 3 * N) return;
    int lane = threadIdx.x & 31;
    int d = w / N, n = w - d * N;

    const float* dh = content + ((size_t)d * N + n) * DD;
    const float* aw = attn_w + d * 256;
    float4 w1 = *(const float4*)(aw + lane * 4);
    float4 w2 = *(const float4*)(aw + 128 + lane * 4);

    float4 s[4];
#pragma unroll
    for (int i = 0; i < 3; i++)
        s[i] = *(const float4*)(neigh + (((size_t)(d * 3 + i)) * N + n) * DD + lane * 4);
    s[3] = *(const float4*)(dh + lane * 4);

    float base = s[3].x * w1.x + s[3].y * w1.y + s[3].z * w1.z + s[3].w * w1.w;
    float l[4];
#pragma unroll
    for (int i = 0; i < 4; i++)
        l[i] = s[i].x * w2.x + s[i].y * w2.y + s[i].z * w2.z + s[i].w * w2.w;

#pragma unroll
    for (int off = 16; off; off >>= 1) {
        base += __shfl_xor_sync(0xffffffffu, base, off);
#pragma unroll
        for (int i = 0; i < 4; i++) l[i] += __shfl_xor_sync(0xffffffffu, l[i], off);
    }

    float b = attn_b[d];
    float mx = -1e30f;
#pragma unroll
    for (int i = 0; i < 4; i++) {
        float v = base + l[i] + b;
        l[i] = v > 0.f ? v : 0.01f * v;
        mx = fmaxf(mx, l[i]);
    }
    float se = 0.f;
#pragma unroll
    for (int i = 0; i < 4; i++) { l[i] = __expf(l[i] - mx); se += l[i]; }
    float inv = 1.f / se;

    float4 o = make_float4(0.f, 0.f, 0.f, 0.f);
#pragma unroll
    for (int i = 0; i < 4; i++) {
        float wi = l[i] * inv;
        o.x += wi * s[i].x; o.y += wi * s[i].y; o.z += wi * s[i].z; o.w += wi * s[i].w;
    }
    *(float4*)(out + ((size_t)d * N + n) * DD + lane * 4) = o;
}

// ---------------------------------------------------------------------------
extern "C" void kernel_launch(void* const* d_in, const int* in_sizes, int n_in,
                              void* d_out, int out_size)
{
    const float* xs[3]   = {(const float*)d_in[0], (const float*)d_in[1], (const float*)d_in[2]};
    const float* Wih_c   = (const float*)d_in[3];
    const float* Whh_c   = (const float*)d_in[4];
    const float* bih_c   = (const float*)d_in[5];
    const float* bhh_c   = (const float*)d_in[6];
    const float* Wih_n   = (const float*)d_in[7];
    const float* Whh_n   = (const float*)d_in[8];
    const float* bih_n   = (const float*)d_in[9];
    const float* bhh_n   = (const float*)d_in[10];
    const float* attn_w  = (const float*)d_in[11];
    const float* attn_b  = (const float*)d_in[12];
    const int*   nbr     = (const int*)d_in[13];
    float* out = (float*)d_out;

    const int N = in_sizes[0] / (3 * DD);   // 30000

    float *gxbuf, *gxn, *content, *neigh;
    cudaGetSymbolAddress((void**)&gxbuf,   g_gxbuf);
    cudaGetSymbolAddress((void**)&gxn,     g_gxn);
    cudaGetSymbolAddress((void**)&content, g_content);
    cudaGetSymbolAddress((void**)&neigh,   g_neigh);

    cudaFuncSetAttribute(gemm_bias,    cudaFuncAttributeMaxDynamicSharedMemorySize, GEMM_SMEM);
    cudaFuncSetAttribute(bilstm_recur, cudaFuncAttributeMaxDynamicSharedMemorySize, RSMEM);

    const int nt = (N + 63) / 64;

    // Stage A+B: content bi-LSTM per feature set (shared weights)
    for (int s = 0; s < 3; s++) {
        gemm_bias<<<dim3((3 * N + 63) / 64, 4), 256, GEMM_SMEM>>>(
            xs[s], Wih_c, bih_c, bhh_c, gxbuf, 3 * N);
        bilstm_recur<<<dim3(nt, 2, 1), 256, RSMEM>>>(
            gxbuf, nullptr, Whh_c, content + (size_t)s * N * DD, N, 3);
    }

    // Stage C: precompute neighbor gate pre-activations per source type
    for (int s = 0; s < 3; s++) {
        gemm_bias<<<dim3(nt, 4), 256, GEMM_SMEM>>>(
            content + (size_t)s * N * DD,
            Wih_n + (size_t)s * ROW * DD,
            bih_n + s * ROW, bhh_n + s * ROW,
            gxn + (size_t)s * N * ROW, N);
    }

    // Stage D: 9 neighbor bi-LSTM reductions (gather pre-activations)
    bilstm_recur<<<dim3(nt, 2, 9), 256, RSMEM>>>(gxn, nbr, Whh_n, neigh, N, 10);

    // Stage E: attention fusion
    attn_fuse<<<(3 * N + 7) / 8, 256>>>(content, neigh, attn_w, attn_b, out, N);
}

// round 11
// speedup vs baseline: 1.1782x; 1.1782x over previous
#include <cuda_runtime.h>
#include <cuda_bf16.h>
#include <cstdint>

// Problem constants (fixed by the dataset): N=30000, C=3, D=128, K=10, H=64
#define DD   128
#define HH   64
#define GATE 256   // 4*H per direction
#define ROW  512   // both directions of gate pre-activations

#define NMAX 30000

// Scratch (static device globals — allocation-free rule)
__device__ __align__(16) float g_gxbuf[(size_t)NMAX * 3 * ROW];   // content gate preacts (reused per s)
__device__ __align__(16) float g_gxn[(size_t)3 * NMAX * ROW];     // neighbor gate preacts per s
__device__ __align__(16) float g_content[(size_t)3 * NMAX * DD];  // content embeddings
__device__ __align__(16) float g_neigh[(size_t)9 * NMAX * DD];    // neigh[d][s][n][128]

__device__ __forceinline__ float sigm(float x) { return __fdividef(1.f, 1.f + __expf(-x)); }
__device__ __forceinline__ float tanh_(float x) { return 2.f * __fdividef(1.f, 1.f + __expf(-2.f * x)) - 1.f; }

__device__ __forceinline__ uint32_t smem_u32(const void* p) {
    uint32_t a;
    asm("{ .reg .u64 t; cvta.to.shared.u64 t, %1; cvt.u32.u64 %0, t; }" : "=r"(a) : "l"(p));
    return a;
}

// warp-level bf16 MMA  D(16x8,f32) += A(16x16,bf16 row) * B(16x8,bf16 col)
__device__ __forceinline__ void mma16816(float& f0, float& f1, float& f2, float& f3,
                                         const uint32_t* a, const uint32_t* b) {
    asm volatile(
        "mma.sync.aligned.m16n8k16.row.col.f32.bf16.bf16.f32 "
        "{%0,%1,%2,%3}, {%4,%5,%6,%7}, {%8,%9}, {%0,%1,%2,%3};"
        : "+f"(f0), "+f"(f1), "+f"(f2), "+f"(f3)
        : "r"(a[0]), "r"(a[1]), "r"(a[2]), "r"(a[3]), "r"(b[0]), "r"(b[1]));
}
__device__ __forceinline__ void ldmx4(uint32_t* r, uint32_t addr) {
    asm volatile("ldmatrix.sync.aligned.m8n8.x4.shared.b16 {%0,%1,%2,%3}, [%4];"
        : "=r"(r[0]), "=r"(r[1]), "=r"(r[2]), "=r"(r[3]) : "r"(addr));
}

// ---------------------------------------------------------------------------
// GEMM: C[m][j] = sum_k A[m][k] * W[j][k] + b1[j] + b2[j]   (R8 version)
// ---------------------------------------------------------------------------
#define GEMM_SMEM ((128 * 68 + 128 * 132) * 4)

__global__ __launch_bounds__(256) void gemm_bias(
    const float* __restrict__ A, const float* __restrict__ W,
    const float* __restrict__ b1, const float* __restrict__ b2,
    float* __restrict__ C, int M)
{
    extern __shared__ float sm[];
    float* Ast = sm;              // [128 k][68 m]
    float* Wst = sm + 128 * 68;   // [128 k][132 j]
    const int tid = threadIdx.x;
    const int bm = blockIdx.x, jc = blockIdx.y;

    for (int q = tid; q < 64 * 32; q += 256) {
        int r = q >> 5;
        int k4 = (q & 31) << 2;
        int gm = bm * 64 + r;
        float4 v = make_float4(0.f, 0.f, 0.f, 0.f);
        if (gm < M) v = *(const float4*)(A + (size_t)gm * 128 + k4);
        Ast[(k4 + 0) * 68 + r] = v.x;
        Ast[(k4 + 1) * 68 + r] = v.y;
        Ast[(k4 + 2) * 68 + r] = v.z;
        Ast[(k4 + 3) * 68 + r] = v.w;
    }
    for (int q = tid; q < 128 * 32; q += 256) {
        int jj = q >> 5;
        int k4 = (q & 31) << 2;
        float4 v = *(const float4*)(W + ((size_t)(jc * 128 + jj)) * 128 + k4);
        Wst[(k4 + 0) * 132 + jj] = v.x;
        Wst[(k4 + 1) * 132 + jj] = v.y;
        Wst[(k4 + 2) * 132 + jj] = v.z;
        Wst[(k4 + 3) * 132 + jj] = v.w;
    }
    __syncthreads();

    const int tx = tid & 15;
    const int ty = tid >> 4;
    float acc[4][8];
#pragma unroll
    for (int i = 0; i < 4; i++)
#pragma unroll
        for (int j = 0; j < 8; j++) acc[i][j] = 0.f;

#pragma unroll 4
    for (int kk = 0; kk < 128; kk++) {
        float4 a  = *(const float4*)(Ast + kk * 68 + (ty << 2));
        float4 w0 = *(const float4*)(Wst + kk * 132 + (tx << 3));
        float4 w1 = *(const float4*)(Wst + kk * 132 + (tx << 3) + 4);
        float av[4] = {a.x, a.y, a.z, a.w};
        float wv[8] = {w0.x, w0.y, w0.z, w0.w, w1.x, w1.y, w1.z, w1.w};
#pragma unroll
        for (int mi = 0; mi < 4; mi++)
#pragma unroll
            for (int ji = 0; ji < 8; ji++) acc[mi][ji] += av[mi] * wv[ji];
    }

    const int jb = (jc << 7) + (tx << 3);
    float bb[8];
#pragma unroll
    for (int ji = 0; ji < 8; ji++) bb[ji] = b1[jb + ji] + b2[jb + ji];

#pragma unroll
    for (int mi = 0; mi < 4; mi++) {
        int gm = (bm << 6) + (ty << 2) + mi;
        if (gm < M) {
            float4 o0 = make_float4(acc[mi][0] + bb[0], acc[mi][1] + bb[1],
                                    acc[mi][2] + bb[2], acc[mi][3] + bb[3]);
            float4 o1 = make_float4(acc[mi][4] + bb[4], acc[mi][5] + bb[5],
                                    acc[mi][6] + bb[6], acc[mi][7] + bb[7]);
            *(float4*)(C + (size_t)gm * ROW + jb)     = o0;
            *(float4*)(C + (size_t)gm * ROW + jb + 4) = o1;
        }
    }
}

// ---------------------------------------------------------------------------
// Scalar bi-LSTM recurrence (R8 version) — used only for the content pass (K=3).
// ---------------------------------------------------------------------------
#define HPITCH 68
#define RSMEM ((64 * 260 + 2 * 64 * HPITCH) * 4 + 64 * 10 * 4)

__global__ __launch_bounds__(256, 2) void bilstm_recur(
    const float* __restrict__ gx, const int* __restrict__ idx,
    const float* __restrict__ Whh, float* __restrict__ out,
    int N, int K)
{
    extern __shared__ float sm[];
    float* WhhT = sm;
    float* Hs0  = sm + 64 * 260;
    float* Hs1  = Hs0 + 64 * HPITCH;
    int*   ids  = (int*)(Hs1 + 64 * HPITCH);

    const int tid = threadIdx.x;
    const int dir = blockIdx.y;

    if (idx) {
        int p = blockIdx.z;
        int d = p / 3, s = p - d * 3;
        gx  += (size_t)s * N * ROW;
        idx += (size_t)(s * 3 + d) * N * K;
        Whh += (size_t)s * 2 * GATE * HH;
        out += (size_t)(d * 3 + s) * N * DD;
    }
    Whh += (size_t)dir * GATE * HH;
    const int node0 = blockIdx.x * 64;

    for (int i = tid; i < GATE * HH; i += 256) {
        int j = i >> 6, k = i & 63;
        WhhT[k * 260 + j] = Whh[i];
    }
    for (int i = tid; i < 64 * HPITCH; i += 256) Hs0[i] = 0.f;
    if (idx) {
        for (int i = tid; i < 64 * K; i += 256) {
            int m = i / K;
            int n = node0 + m;
            ids[i] = (n < N) ? idx[(size_t)n * K + (i - m * K)] : 0;
        }
    }
    __syncthreads();

    const int ng = tid >> 5;
    const int kg = tid & 31;
    const int u0 = kg << 1;
    const int mbase = ng << 3;

    float c[2][8], hsum[2][8];
#pragma unroll
    for (int u = 0; u < 2; u++)
#pragma unroll
        for (int i = 0; i < 8; i++) { c[u][i] = 0.f; hsum[u][i] = 0.f; }

    const float* gbase = gx + dir * GATE + u0;

    for (int t = 0; t < K; t++) {
        const int tt = dir ? (K - 1 - t) : t;

        float A[4][2][8];
#pragma unroll
        for (int i = 0; i < 8; i++) {
            int m = mbase + i;
            size_t row;
            if (idx) {
                row = (size_t)ids[m * K + tt];
            } else {
                int n = node0 + m;
                row = (size_t)(n < N ? n : 0) * K + tt;
            }
            const float* pr = gbase + row * ROW;
#pragma unroll
            for (int g = 0; g < 4; g++) {
                float2 v = *(const float2*)(pr + (g << 6));
                A[g][0][i] = v.x;
                A[g][1][i] = v.y;
            }
        }

        const float* Hr = (t & 1) ? Hs1 : Hs0;
        float*       Hw = (t & 1) ? Hs0 : Hs1;

#pragma unroll 2
        for (int kk = 0; kk < 64; kk++) {
            float4 h0 = *(const float4*)(Hr + kk * HPITCH + mbase);
            float4 h1 = *(const float4*)(Hr + kk * HPITCH + mbase + 4);
            const float* wr = WhhT + kk * 260 + u0;
#pragma unroll
            for (int g = 0; g < 4; g++) {
                float2 w = *(const float2*)(wr + (g << 6));
                A[g][0][0] += h0.x * w.x; A[g][0][1] += h0.y * w.x;
                A[g][0][2] += h0.z * w.x; A[g][0][3] += h0.w * w.x;
                A[g][0][4] += h1.x * w.x; A[g][0][5] += h1.y * w.x;
                A[g][0][6] += h1.z * w.x; A[g][0][7] += h1.w * w.x;
                A[g][1][0] += h0.x * w.y; A[g][1][1] += h0.y * w.y;
                A[g][1][2] += h0.z * w.y; A[g][1][3] += h0.w * w.y;
                A[g][1][4] += h1.x * w.y; A[g][1][5] += h1.y * w.y;
                A[g][1][6] += h1.z * w.y; A[g][1][7] += h1.w * w.y;
            }
        }

#pragma unroll
        for (int u = 0; u < 2; u++) {
            float hv[8];
#pragma unroll
            for (int i = 0; i < 8; i++) {
                float iv = A[0][u][i], fv = A[1][u][i];
                float gv = A[2][u][i], ov = A[3][u][i];
                c[u][i] = sigm(fv) * c[u][i] + sigm(iv) * tanh_(gv);
                hv[i] = sigm(ov) * tanh_(c[u][i]);
                hsum[u][i] += hv[i];
            }
            *(float4*)(Hw + (u0 + u) * HPITCH + mbase) =
                make_float4(hv[0], hv[1], hv[2], hv[3]);
            *(float4*)(Hw + (u0 + u) * HPITCH + mbase + 4) =
                make_float4(hv[4], hv[5], hv[6], hv[7]);
        }
        __syncthreads();
    }

    const float inv = 1.f / (float)K;
#pragma unroll
    for (int i = 0; i < 8; i++) {
        int n = node0 + mbase + i;
        if (n < N) {
            *(float2*)(out + (size_t)n * DD + dir * HH + u0) =
                make_float2(hsum[0][i] * inv, hsum[1][i] * inv);
        }
    }
}

// ---------------------------------------------------------------------------
// Stage D: warp-MMA bi-LSTM recurrence (mma.sync m16n8k16 bf16, split hi/lo).
// CTA = 64 nodes, one (s,d,dir), K=10, 256 threads (8 warps).
// Per step: D[64x256] = Hhi@Whi^T + Hhi@Wlo^T + Hlo@Whi^T  (fp32 accum)
//   A (H) bf16 hi/lo tiles in SMEM, pitch 144B, read via ldmatrix.x4.
//   B (Whh) fragments converted from gmem fp32 once, persistent in registers.
//   Each warp: n-slice of 32 gate cols; 4m x 4n x 4k x 3 = 192 MMAs/step.
// D staged in SMEM (fp32, pitch 264 words); SIMT gate phase adds gathered gx
// preacts (gmem), does exact fp32 gate math, writes H back as bf16 hi/lo.
// grid: (ceil(N/64), 2, 9), z = s*3 + d (same-s adjacent -> gx L2 reuse).
// ---------------------------------------------------------------------------
#define KD 10
#define O_AHI 2560                 // after ids (64*10*4)
#define O_ALO (O_AHI + 64 * 144)
#define O_D   (O_ALO + 64 * 144)   // 20992
#define DPW   264                  // D row pitch (words)
#define MM_SMEM (O_D + 64 * DPW * 4)   // 88576

__global__ __launch_bounds__(256) void bilstm_mma(
    const float* __restrict__ gxn, const int* __restrict__ nbr,
    const float* __restrict__ Whh_n, float* __restrict__ neigh, int N)
{
    extern __shared__ char smc[];
    int*   ids = (int*)smc;
    float* Dp  = (float*)(smc + O_D);
    const uint32_t sb = smem_u32(smc);

    const int tid = threadIdx.x;
    const int lane = tid & 31, w = tid >> 5;
    const int dir = blockIdx.y;
    const int z = blockIdx.z;
    const int s = z / 3, d = z - s * 3;

    const float* gx  = gxn + (size_t)s * N * ROW;
    const int*   idx = nbr + (size_t)(s * 3 + d) * N * KD;
    const float* Whh = Whh_n + ((size_t)s * 2 + dir) * GATE * HH;
    float*       out = neigh + (size_t)(d * 3 + s) * N * DD;
    const int node0 = blockIdx.x * 64;

    // Stage gather indices
    for (int i = tid; i < 64 * KD; i += 256) {
        int m = i / KD;
        int n = node0 + m;
        ids[i] = (n < N) ? idx[(size_t)n * KD + (i - m * KD)] : 0;
    }
    // Zero A tiles (H=0), hi+lo contiguous
    for (int i = tid; i < (2 * 64 * 144) / 4; i += 256)
        ((float*)(smc + O_AHI))[i] = 0.f;

    // Persistent B fragments (split-bf16) straight from gmem fp32 Whh.
    // m16n8k16 B frag: reg0 = B[k0..k0+1][n], reg1 = B[k0+8..k0+9][n],
    //   n = nbase + nt*8 + lane/4, k0 = kt*16 + 2*(lane&3).
    const int nbase = w * 32;
    uint32_t bh[4][4][2], bl[4][4][2];
    {
        const int jr = nbase + (lane >> 2);
        const int kq = (lane & 3) << 1;
#pragma unroll
        for (int nt = 0; nt < 4; nt++) {
            const float* wr = Whh + (size_t)(jr + nt * 8) * HH;
#pragma unroll
            for (int kt = 0; kt < 4; kt++) {
#pragma unroll
                for (int hb = 0; hb < 2; hb++) {
                    float2 x = *(const float2*)(wr + kt * 16 + kq + hb * 8);
                    __nv_bfloat16 hx = __float2bfloat16_rn(x.x);
                    __nv_bfloat16 hy = __float2bfloat16_rn(x.y);
                    float rx = x.x - __bfloat162float(hx);
                    float ry = x.y - __bfloat162float(hy);
                    __nv_bfloat16 lx = __float2bfloat16_rn(rx);
                    __nv_bfloat16 ly = __float2bfloat16_rn(ry);
                    bh[nt][kt][hb] = ((uint32_t)__bfloat16_as_ushort(hy) << 16)
                                   | (uint32_t)__bfloat16_as_ushort(hx);
                    bl[nt][kt][hb] = ((uint32_t)__bfloat16_as_ushort(ly) << 16)
                                   | (uint32_t)__bfloat16_as_ushort(lx);
                }
            }
        }
    }
    __syncthreads();

    // ldmatrix lane addressing for 16x16 A tiles (pitch 144B):
    //   lanes 0-7: rows 0-7 cols 0-7 | 8-15: rows 8-15 | 16-23: +16B | 24-31: both
    const int gA = lane >> 3, rA = lane & 7;
    const int arow = ((gA & 1) << 3) + rA;
    const int acol = (gA >> 1) << 4;

    // Gate-phase ownership: u = (tid&15) + 16*un, n = (tid>>4) + 16*nn
    const int u0 = tid & 15, nr0 = tid >> 4;
    float c[4][4], hsum[4][4];
#pragma unroll
    for (int a = 0; a < 4; a++)
#pragma unroll
        for (int b = 0; b < 4; b++) { c[a][b] = 0.f; hsum[a][b] = 0.f; }

    for (int t = 0; t < KD; t++) {
        // ---- MMA phase: D = H @ Whh^T (3-term split-bf16) ----
#pragma unroll
        for (int mt = 0; mt < 4; mt++) {
            uint32_t ah[4][4], al[4][4];
            const uint32_t abase = sb + O_AHI + (uint32_t)(mt * 16 + arow) * 144 + acol;
#pragma unroll
            for (int kt = 0; kt < 4; kt++) {
                ldmx4(ah[kt], abase + kt * 32);
                ldmx4(al[kt], abase + (O_ALO - O_AHI) + kt * 32);
            }
#pragma unroll
            for (int nt = 0; nt < 4; nt++) {
                float f0 = 0.f, f1 = 0.f, f2 = 0.f, f3 = 0.f;
#pragma unroll
                for (int kt = 0; kt < 4; kt++) {
                    mma16816(f0, f1, f2, f3, ah[kt], bh[nt][kt]);
                    mma16816(f0, f1, f2, f3, ah[kt], bl[nt][kt]);
                    mma16816(f0, f1, f2, f3, al[kt], bh[nt][kt]);
                }
                const int row = mt * 16 + (lane >> 2);
                const int col = nbase + nt * 8 + ((lane & 3) << 1);
                *(float2*)(Dp + row * DPW + col)       = make_float2(f0, f1);
                *(float2*)(Dp + (row + 8) * DPW + col) = make_float2(f2, f3);
            }
        }
        __syncthreads();

        // ---- Gate phase: add gx preacts, LSTM math, write H (bf16 hi/lo) ----
        const int tt = dir ? (KD - 1 - t) : t;
#pragma unroll
        for (int un = 0; un < 4; un++) {
            const int u = u0 + un * 16;
#pragma unroll
            for (int nn = 0; nn < 4; nn++) {
                const int n = nr0 + nn * 16;
                const float* gp = gx + (size_t)ids[n * KD + tt] * ROW + dir * GATE;
                float iv = Dp[n * DPW + u]         + gp[u];
                float fv = Dp[n * DPW + 64 + u]    + gp[64 + u];
                float gv = Dp[n * DPW + 128 + u]   + gp[128 + u];
                float ov = Dp[n * DPW + 192 + u]   + gp[192 + u];
                float cc = c[un][nn];
                cc = sigm(fv) * cc + sigm(iv) * tanh_(gv);
                c[un][nn] = cc;
                float h = sigm(ov) * tanh_(cc);
                hsum[un][nn] += h;
                __nv_bfloat16 hb = __float2bfloat16_rn(h);
                __nv_bfloat16 lb = __float2bfloat16_rn(h - __bfloat162float(hb));
                *(__nv_bfloat16*)(smc + O_AHI + n * 144 + u * 2) = hb;
                *(__nv_bfloat16*)(smc + O_ALO + n * 144 + u * 2) = lb;
            }
        }
        __syncthreads();
    }

    // Output: mean over K steps
    const float inv = 1.f / (float)KD;
#pragma unroll
    for (int un = 0; un < 4; un++) {
        const int u = u0 + un * 16;
#pragma unroll
        for (int nn = 0; nn < 4; nn++) {
            const int gn = node0 + nr0 + nn * 16;
            if (gn < N)
                out[(size_t)gn * DD + dir * HH + u] = hsum[un][nn] * inv;
        }
    }
}

// ---------------------------------------------------------------------------
// Attention fusion: one warp per (d, n).
// ---------------------------------------------------------------------------
__global__ void attn_fuse(const float* __restrict__ content,
                          const float* __restrict__ neigh,
                          const float* __restrict__ attn_w,
                          const float* __restrict__ attn_b,
                          float* __restrict__ out, int N)
{
    int w = (blockIdx.x * blockDim.x + threadIdx.x) >> 5;
    if (w >= 3 * N) return;
    int lane = threadIdx.x & 31;
    int d = w / N, n = w - d * N;

    const float* dh = content + ((size_t)d * N + n) * DD;
    const float* aw = attn_w + d * 256;
    float4 w1 = *(const float4*)(aw + lane * 4);
    float4 w2 = *(const float4*)(aw + 128 + lane * 4);

    float4 s[4];
#pragma unroll
    for (int i = 0; i < 3; i++)
        s[i] = *(const float4*)(neigh + (((size_t)(d * 3 + i)) * N + n) * DD + lane * 4);
    s[3] = *(const float4*)(dh + lane * 4);

    float base = s[3].x * w1.x + s[3].y * w1.y + s[3].z * w1.z + s[3].w * w1.w;
    float l[4];
#pragma unroll
    for (int i = 0; i < 4; i++)
        l[i] = s[i].x * w2.x + s[i].y * w2.y + s[i].z * w2.z + s[i].w * w2.w;

#pragma unroll
    for (int off = 16; off; off >>= 1) {
        base += __shfl_xor_sync(0xffffffffu, base, off);
#pragma unroll
        for (int i = 0; i < 4; i++) l[i] += __shfl_xor_sync(0xffffffffu, l[i], off);
    }

    float b = attn_b[d];
    float mx = -1e30f;
#pragma unroll
    for (int i = 0; i < 4; i++) {
        float v = base + l[i] + b;
        l[i] = v > 0.f ? v : 0.01f * v;
        mx = fmaxf(mx, l[i]);
    }
    float se = 0.f;
#pragma unroll
    for (int i = 0; i < 4; i++) { l[i] = __expf(l[i] - mx); se += l[i]; }
    float inv = 1.f / se;

    float4 o = make_float4(0.f, 0.f, 0.f, 0.f);
#pragma unroll
    for (int i = 0; i < 4; i++) {
        float wi = l[i] * inv;
        o.x += wi * s[i].x; o.y += wi * s[i].y; o.z += wi * s[i].z; o.w += wi * s[i].w;
    }
    *(float4*)(out + ((size_t)d * N + n) * DD + lane * 4) = o;
}

// ---------------------------------------------------------------------------
extern "C" void kernel_launch(void* const* d_in, const int* in_sizes, int n_in,
                              void* d_out, int out_size)
{
    const float* xs[3]   = {(const float*)d_in[0], (const float*)d_in[1], (const float*)d_in[2]};
    const float* Wih_c   = (const float*)d_in[3];
    const float* Whh_c   = (const float*)d_in[4];
    const float* bih_c   = (const float*)d_in[5];
    const float* bhh_c   = (const float*)d_in[6];
    const float* Wih_n   = (const float*)d_in[7];
    const float* Whh_n   = (const float*)d_in[8];
    const float* bih_n   = (const float*)d_in[9];
    const float* bhh_n   = (const float*)d_in[10];
    const float* attn_w  = (const float*)d_in[11];
    const float* attn_b  = (const float*)d_in[12];
    const int*   nbr     = (const int*)d_in[13];
    float* out = (float*)d_out;

    const int N = in_sizes[0] / (3 * DD);   // 30000

    float *gxbuf, *gxn, *content, *neigh;
    cudaGetSymbolAddress((void**)&gxbuf,   g_gxbuf);
    cudaGetSymbolAddress((void**)&gxn,     g_gxn);
    cudaGetSymbolAddress((void**)&content, g_content);
    cudaGetSymbolAddress((void**)&neigh,   g_neigh);

    cudaFuncSetAttribute(gemm_bias,    cudaFuncAttributeMaxDynamicSharedMemorySize, GEMM_SMEM);
    cudaFuncSetAttribute(bilstm_recur, cudaFuncAttributeMaxDynamicSharedMemorySize, RSMEM);
    cudaFuncSetAttribute(bilstm_mma,   cudaFuncAttributeMaxDynamicSharedMemorySize, MM_SMEM);

    const int nt = (N + 63) / 64;

    // Stage A+B: content bi-LSTM per feature set (shared weights)
    for (int s = 0; s < 3; s++) {
        gemm_bias<<<dim3((3 * N + 63) / 64, 4), 256, GEMM_SMEM>>>(
            xs[s], Wih_c, bih_c, bhh_c, gxbuf, 3 * N);
        bilstm_recur<<<dim3(nt, 2, 1), 256, RSMEM>>>(
            gxbuf, nullptr, Whh_c, content + (size_t)s * N * DD, N, 3);
    }

    // Stage C: precompute neighbor gate pre-activations per source type
    for (int s = 0; s < 3; s++) {
        gemm_bias<<<dim3(nt, 4), 256, GEMM_SMEM>>>(
            content + (size_t)s * N * DD,
            Wih_n + (size_t)s * ROW * DD,
            bih_n + s * ROW, bhh_n + s * ROW,
            gxn + (size_t)s * N * ROW, N);
    }

    // Stage D: 9 neighbor bi-LSTM reductions on warp MMAs (split-bf16)
    bilstm_mma<<<dim3(nt, 2, 9), 256, MM_SMEM>>>(gxn, nbr, Whh_n, neigh, N);

    // Stage E: attention fusion
    attn_fuse<<<(3 * N + 7) / 8, 256>>>(content, neigh, attn_w, attn_b, out, N);
}

// round 12
// speedup vs baseline: 1.4714x; 1.2488x over previous
#include <cuda_runtime.h>
#include <cuda_bf16.h>
#include <cstdint>

// Problem constants (fixed by the dataset): N=30000, C=3, D=128, K=10, H=64
#define DD   128
#define HH   64
#define GATE 256   // 4*H per direction
#define ROW  512   // both directions of gate pre-activations

#define NMAX 30000

// Scratch (static device globals — allocation-free rule)
__device__ __align__(16) float g_gxbuf[(size_t)NMAX * 3 * ROW];   // content gate preacts (reused per s)
__device__ __align__(16) float g_gxn[(size_t)3 * NMAX * ROW];     // neighbor gate preacts per s
__device__ __align__(16) float g_content[(size_t)3 * NMAX * DD];  // content embeddings
__device__ __align__(16) float g_neigh[(size_t)9 * NMAX * DD];    // neigh[d][s][n][128]

__device__ __forceinline__ float sigm(float x) { return __fdividef(1.f, 1.f + __expf(-x)); }
__device__ __forceinline__ float tanh_(float x) { return 2.f * __fdividef(1.f, 1.f + __expf(-2.f * x)) - 1.f; }

__device__ __forceinline__ uint32_t smem_u32(const void* p) {
    uint32_t a;
    asm("{ .reg .u64 t; cvta.to.shared.u64 t, %1; cvt.u32.u64 %0, t; }" : "=r"(a) : "l"(p));
    return a;
}

// warp-level bf16 MMA  D(16x8,f32) += A(16x16,bf16 row) * B(16x8,bf16 col)
__device__ __forceinline__ void mma16816(float& f0, float& f1, float& f2, float& f3,
                                         const uint32_t* a, const uint32_t* b) {
    asm volatile(
        "mma.sync.aligned.m16n8k16.row.col.f32.bf16.bf16.f32 "
        "{%0,%1,%2,%3}, {%4,%5,%6,%7}, {%8,%9}, {%0,%1,%2,%3};"
        : "+f"(f0), "+f"(f1), "+f"(f2), "+f"(f3)
        : "r"(a[0]), "r"(a[1]), "r"(a[2]), "r"(a[3]), "r"(b[0]), "r"(b[1]));
}
__device__ __forceinline__ void ldmx4(uint32_t* r, uint32_t addr) {
    asm volatile("ldmatrix.sync.aligned.m8n8.x4.shared.b16 {%0,%1,%2,%3}, [%4];"
        : "=r"(r[0]), "=r"(r[1]), "=r"(r[2]), "=r"(r[3]) : "r"(addr));
}

// ---------------------------------------------------------------------------
// GEMM: C[m][j] = sum_k A[m][k] * W[j][k] + b1[j] + b2[j]   (R8 version)
// ---------------------------------------------------------------------------
#define GEMM_SMEM ((128 * 68 + 128 * 132) * 4)

__global__ __launch_bounds__(256) void gemm_bias(
    const float* __restrict__ A, const float* __restrict__ W,
    const float* __restrict__ b1, const float* __restrict__ b2,
    float* __restrict__ C, int M)
{
    extern __shared__ float sm[];
    float* Ast = sm;              // [128 k][68 m]
    float* Wst = sm + 128 * 68;   // [128 k][132 j]
    const int tid = threadIdx.x;
    const int bm = blockIdx.x, jc = blockIdx.y;

    for (int q = tid; q < 64 * 32; q += 256) {
        int r = q >> 5;
        int k4 = (q & 31) << 2;
        int gm = bm * 64 + r;
        float4 v = make_float4(0.f, 0.f, 0.f, 0.f);
        if (gm < M) v = *(const float4*)(A + (size_t)gm * 128 + k4);
        Ast[(k4 + 0) * 68 + r] = v.x;
        Ast[(k4 + 1) * 68 + r] = v.y;
        Ast[(k4 + 2) * 68 + r] = v.z;
        Ast[(k4 + 3) * 68 + r] = v.w;
    }
    for (int q = tid; q < 128 * 32; q += 256) {
        int jj = q >> 5;
        int k4 = (q & 31) << 2;
        float4 v = *(const float4*)(W + ((size_t)(jc * 128 + jj)) * 128 + k4);
        Wst[(k4 + 0) * 132 + jj] = v.x;
        Wst[(k4 + 1) * 132 + jj] = v.y;
        Wst[(k4 + 2) * 132 + jj] = v.z;
        Wst[(k4 + 3) * 132 + jj] = v.w;
    }
    __syncthreads();

    const int tx = tid & 15;
    const int ty = tid >> 4;
    float acc[4][8];
#pragma unroll
    for (int i = 0; i < 4; i++)
#pragma unroll
        for (int j = 0; j < 8; j++) acc[i][j] = 0.f;

#pragma unroll 4
    for (int kk = 0; kk < 128; kk++) {
        float4 a  = *(const float4*)(Ast + kk * 68 + (ty << 2));
        float4 w0 = *(const float4*)(Wst + kk * 132 + (tx << 3));
        float4 w1 = *(const float4*)(Wst + kk * 132 + (tx << 3) + 4);
        float av[4] = {a.x, a.y, a.z, a.w};
        float wv[8] = {w0.x, w0.y, w0.z, w0.w, w1.x, w1.y, w1.z, w1.w};
#pragma unroll
        for (int mi = 0; mi < 4; mi++)
#pragma unroll
            for (int ji = 0; ji < 8; ji++) acc[mi][ji] += av[mi] * wv[ji];
    }

    const int jb = (jc << 7) + (tx << 3);
    float bb[8];
#pragma unroll
    for (int ji = 0; ji < 8; ji++) bb[ji] = b1[jb + ji] + b2[jb + ji];

#pragma unroll
    for (int mi = 0; mi < 4; mi++) {
        int gm = (bm << 6) + (ty << 2) + mi;
        if (gm < M) {
            float4 o0 = make_float4(acc[mi][0] + bb[0], acc[mi][1] + bb[1],
                                    acc[mi][2] + bb[2], acc[mi][3] + bb[3]);
            float4 o1 = make_float4(acc[mi][4] + bb[4], acc[mi][5] + bb[5],
                                    acc[mi][6] + bb[6], acc[mi][7] + bb[7]);
            *(float4*)(C + (size_t)gm * ROW + jb)     = o0;
            *(float4*)(C + (size_t)gm * ROW + jb + 4) = o1;
        }
    }
}

// ---------------------------------------------------------------------------
// Unified bi-LSTM recurrence on warp MMAs (split-bf16 hi/lo, fp32 accum).
// v2: gate-major B permutation -> gate math fully in registers.
//
// CTA = 64 nodes, one (s,d,dir), 256 threads (8 warps).
// Warp w owns hidden-unit band uw = w*8..w*8+7 across ALL 4 gates:
//   B frag for gate g covers cols j = g*64 + uw + (lane>>2).
// After the 3-term MMA (Hhi@Whi + Hhi@Wlo + Hlo@Whi), each lane holds
// (i,f,g,o) for its (node-row, u-pair) directly in fragments — no SMEM D.
// gx pre-activations are loaded straight into the accumulators (C init).
// H (bf16 hi/lo) lives in double-buffered SMEM A tiles -> ONE barrier/step.
//
// neighbor mode (nbr != null): grid (ceil(N/64), 2, 9), z = s*3+d; gathers
//   rows via nbr. content mode (nbr == null): row = n*K + t, params direct.
// ---------------------------------------------------------------------------
#define O_A   2560                 // after ids (64*10*4 max)
#define ABUF  9216                 // 64 rows * 144B (one hi or lo tile)
#define ASTEP 18432                // hi+lo pair
#define MM_SMEM (O_A + 2 * ASTEP)  // 39424

__global__ __launch_bounds__(256) void bilstm_mma(
    const float* __restrict__ gxn, const int* __restrict__ nbr,
    const float* __restrict__ WhhP, float* __restrict__ outP, int N, int K)
{
    extern __shared__ char smc[];
    int* ids = (int*)smc;
    const uint32_t sb = smem_u32(smc);

    const int tid = threadIdx.x;
    const int lane = tid & 31, w = tid >> 5;
    const int dir = blockIdx.y;

    const float* gx = gxn;
    const float* Whh = WhhP;
    float* out = outP;
    const int* idx = nbr;
    if (nbr) {
        int z = blockIdx.z;
        int s = z / 3, d = z - s * 3;
        gx  += (size_t)s * N * ROW;
        idx  = nbr + (size_t)(s * 3 + d) * N * K;
        Whh += (size_t)s * 2 * GATE * HH;
        out += (size_t)(d * 3 + s) * N * DD;
    }
    Whh += (size_t)dir * GATE * HH;
    const int node0 = blockIdx.x * 64;

    // Stage gather indices (neighbor mode only)
    if (nbr) {
        for (int i = tid; i < 64 * K; i += 256) {
            int m = i / K;
            int n = node0 + m;
            ids[i] = (n < N) ? idx[(size_t)n * K + (i - m * K)] : 0;
        }
    }
    // Zero A buffer 0 (hi+lo): H = 0
    for (int i = tid; i < ASTEP / 4; i += 256)
        ((float*)(smc + O_A))[i] = 0.f;

    // Persistent B fragments, gate-major permutation (split-bf16 from fp32 Whh).
    // frag reg0 = W[j][k0..k0+1], reg1 = W[j][k0+8..k0+9];
    //   j = g*64 + uw + (lane>>2), k0 = kt*16 + 2*(lane&3).
    const int uw = w << 3;
    uint32_t bh[4][4][2], bl[4][4][2];
    {
        const int jr = uw + (lane >> 2);
        const int kq = (lane & 3) << 1;
#pragma unroll
        for (int g = 0; g < 4; g++) {
            const float* wr = Whh + (size_t)(g * 64 + jr) * HH;
#pragma unroll
            for (int kt = 0; kt < 4; kt++) {
#pragma unroll
                for (int hb = 0; hb < 2; hb++) {
                    float2 x = *(const float2*)(wr + kt * 16 + kq + hb * 8);
                    __nv_bfloat16 hx = __float2bfloat16_rn(x.x);
                    __nv_bfloat16 hy = __float2bfloat16_rn(x.y);
                    __nv_bfloat16 lx = __float2bfloat16_rn(x.x - __bfloat162float(hx));
                    __nv_bfloat16 ly = __float2bfloat16_rn(x.y - __bfloat162float(hy));
                    bh[g][kt][hb] = ((uint32_t)__bfloat16_as_ushort(hy) << 16)
                                  | (uint32_t)__bfloat16_as_ushort(hx);
                    bl[g][kt][hb] = ((uint32_t)__bfloat16_as_ushort(ly) << 16)
                                  | (uint32_t)__bfloat16_as_ushort(lx);
                }
            }
        }
    }
    __syncthreads();

    // ldmatrix lane addressing for 16x16 A tiles (pitch 144B)
    const int gA = lane >> 3, rA = lane & 7;
    const int arow = ((gA & 1) << 3) + rA;
    const int acol = (gA >> 1) << 4;

    // Per-thread D ownership: rows mt*16 + rq (+8), u-pair (u, u+1)
    const int rq = lane >> 2;
    const int u = uw + ((lane & 3) << 1);

    float c[4][4], hsum[4][4];   // [mt][pos]: 0,1 = (r0,u/u+1); 2,3 = (r1,u/u+1)
#pragma unroll
    for (int a = 0; a < 4; a++)
#pragma unroll
        for (int b = 0; b < 4; b++) { c[a][b] = 0.f; hsum[a][b] = 0.f; }

    const float* gbase = gx + dir * GATE + u;

    for (int t = 0; t < K; t++) {
        const int tt = dir ? (K - 1 - t) : t;
        const uint32_t rb = sb + O_A + (uint32_t)(t & 1) * ASTEP;         // read buf
        char* wbp = smc + O_A + ((t + 1) & 1) * ASTEP;                    // write buf

#pragma unroll
        for (int mt = 0; mt < 4; mt++) {
            const int m0 = (mt << 4) + rq, m1 = m0 + 8;
            size_t row0, row1;
            if (nbr) {
                row0 = (size_t)ids[m0 * K + tt];
                row1 = (size_t)ids[m1 * K + tt];
            } else {
                int n0 = node0 + m0, n1 = node0 + m1;
                row0 = (size_t)(n0 < N ? n0 : N - 1) * K + tt;
                row1 = (size_t)(n1 < N ? n1 : N - 1) * K + tt;
            }
            const float* p0 = gbase + row0 * ROW;
            const float* p1 = gbase + row1 * ROW;

            // A fragments (hi/lo) for this 16-row tile
            uint32_t ah[4][4], al[4][4];
            const uint32_t ab = rb + (uint32_t)((mt << 4) + arow) * 144 + acol;
#pragma unroll
            for (int kt = 0; kt < 4; kt++) {
                ldmx4(ah[kt], ab + kt * 32);
                ldmx4(al[kt], ab + ABUF + kt * 32);
            }

            // Accumulators init from gx, then 3-term MMA per gate
            float fg[4][4];
#pragma unroll
            for (int g = 0; g < 4; g++) {
                float2 v0 = *(const float2*)(p0 + (g << 6));
                float2 v1 = *(const float2*)(p1 + (g << 6));
                float f0 = v0.x, f1 = v0.y, f2 = v1.x, f3 = v1.y;
#pragma unroll
                for (int kt = 0; kt < 4; kt++) {
                    mma16816(f0, f1, f2, f3, ah[kt], bh[g][kt]);
                    mma16816(f0, f1, f2, f3, ah[kt], bl[g][kt]);
                    mma16816(f0, f1, f2, f3, al[kt], bh[g][kt]);
                }
                fg[g][0] = f0; fg[g][1] = f1; fg[g][2] = f2; fg[g][3] = f3;
            }

            // Gate math in registers; write new H (bf16 hi/lo) to next buffer
            unsigned short hh[4], hl[4];
#pragma unroll
            for (int pos = 0; pos < 4; pos++) {
                float cc = c[mt][pos];
                cc = sigm(fg[1][pos]) * cc + sigm(fg[0][pos]) * tanh_(fg[2][pos]);
                c[mt][pos] = cc;
                float h = sigm(fg[3][pos]) * tanh_(cc);
                hsum[mt][pos] += h;
                __nv_bfloat16 hb16 = __float2bfloat16_rn(h);
                __nv_bfloat16 lb16 = __float2bfloat16_rn(h - __bfloat162float(hb16));
                hh[pos] = __bfloat16_as_ushort(hb16);
                hl[pos] = __bfloat16_as_ushort(lb16);
            }
            // rows m0 (pos 0,1) and m1 (pos 2,3), u-pair at byte offset u*2
            *(uint32_t*)(wbp + m0 * 144 + u * 2) =
                (uint32_t)hh[0] | ((uint32_t)hh[1] << 16);
            *(uint32_t*)(wbp + ABUF + m0 * 144 + u * 2) =
                (uint32_t)hl[0] | ((uint32_t)hl[1] << 16);
            *(uint32_t*)(wbp + m1 * 144 + u * 2) =
                (uint32_t)hh[2] | ((uint32_t)hh[3] << 16);
            *(uint32_t*)(wbp + ABUF + m1 * 144 + u * 2) =
                (uint32_t)hl[2] | ((uint32_t)hl[3] << 16);
        }
        __syncthreads();   // next buffer complete; prior buffer reads all done
    }

    // Output: mean over K steps
    const float inv = 1.f / (float)K;
#pragma unroll
    for (int mt = 0; mt < 4; mt++) {
        const int n0 = node0 + (mt << 4) + rq;
        const int n1 = n0 + 8;
        if (n0 < N)
            *(float2*)(out + (size_t)n0 * DD + dir * HH + u) =
                make_float2(hsum[mt][0] * inv, hsum[mt][1] * inv);
        if (n1 < N)
            *(float2*)(out + (size_t)n1 * DD + dir * HH + u) =
                make_float2(hsum[mt][2] * inv, hsum[mt][3] * inv);
    }
}

// ---------------------------------------------------------------------------
// Attention fusion: one warp per (d, n).
// ---------------------------------------------------------------------------
__global__ void attn_fuse(const float* __restrict__ content,
                          const float* __restrict__ neigh,
                          const float* __restrict__ attn_w,
                          const float* __restrict__ attn_b,
                          float* __restrict__ out, int N)
{
    int w = (blockIdx.x * blockDim.x + threadIdx.x) >> 5;
    if (w >= 3 * N) return;
    int lane = threadIdx.x & 31;
    int d = w / N, n = w - d * N;

    const float* dh = content + ((size_t)d * N + n) * DD;
    const float* aw = attn_w + d * 256;
    float4 w1 = *(const float4*)(aw + lane * 4);
    float4 w2 = *(const float4*)(aw + 128 + lane * 4);

    float4 s[4];
#pragma unroll
    for (int i = 0; i < 3; i++)
        s[i] = *(const float4*)(neigh + (((size_t)(d * 3 + i)) * N + n) * DD + lane * 4);
    s[3] = *(const float4*)(dh + lane * 4);

    float base = s[3].x * w1.x + s[3].y * w1.y + s[3].z * w1.z + s[3].w * w1.w;
    float l[4];
#pragma unroll
    for (int i = 0; i < 4; i++)
        l[i] = s[i].x * w2.x + s[i].y * w2.y + s[i].z * w2.z + s[i].w * w2.w;

#pragma unroll
    for (int off = 16; off; off >>= 1) {
        base += __shfl_xor_sync(0xffffffffu, base, off);
#pragma unroll
        for (int i = 0; i < 4; i++) l[i] += __shfl_xor_sync(0xffffffffu, l[i], off);
    }

    float b = attn_b[d];
    float mx = -1e30f;
#pragma unroll
    for (int i = 0; i < 4; i++) {
        float v = base + l[i] + b;
        l[i] = v > 0.f ? v : 0.01f * v;
        mx = fmaxf(mx, l[i]);
    }
    float se = 0.f;
#pragma unroll
    for (int i = 0; i < 4; i++) { l[i] = __expf(l[i] - mx); se += l[i]; }
    float inv = 1.f / se;

    float4 o = make_float4(0.f, 0.f, 0.f, 0.f);
#pragma unroll
    for (int i = 0; i < 4; i++) {
        float wi = l[i] * inv;
        o.x += wi * s[i].x; o.y += wi * s[i].y; o.z += wi * s[i].z; o.w += wi * s[i].w;
    }
    *(float4*)(out + ((size_t)d * N + n) * DD + lane * 4) = o;
}

// ---------------------------------------------------------------------------
extern "C" void kernel_launch(void* const* d_in, const int* in_sizes, int n_in,
                              void* d_out, int out_size)
{
    const float* xs[3]   = {(const float*)d_in[0], (const float*)d_in[1], (const float*)d_in[2]};
    const float* Wih_c   = (const float*)d_in[3];
    const float* Whh_c   = (const float*)d_in[4];
    const float* bih_c   = (const float*)d_in[5];
    const float* bhh_c   = (const float*)d_in[6];
    const float* Wih_n   = (const float*)d_in[7];
    const float* Whh_n   = (const float*)d_in[8];
    const float* bih_n   = (const float*)d_in[9];
    const float* bhh_n   = (const float*)d_in[10];
    const float* attn_w  = (const float*)d_in[11];
    const float* attn_b  = (const float*)d_in[12];
    const int*   nbr     = (const int*)d_in[13];
    float* out = (float*)d_out;

    const int N = in_sizes[0] / (3 * DD);   // 30000

    float *gxbuf, *gxn, *content, *neigh;
    cudaGetSymbolAddress((void**)&gxbuf,   g_gxbuf);
    cudaGetSymbolAddress((void**)&gxn,     g_gxn);
    cudaGetSymbolAddress((void**)&content, g_content);
    cudaGetSymbolAddress((void**)&neigh,   g_neigh);

    cudaFuncSetAttribute(gemm_bias,  cudaFuncAttributeMaxDynamicSharedMemorySize, GEMM_SMEM);
    cudaFuncSetAttribute(bilstm_mma, cudaFuncAttributeMaxDynamicSharedMemorySize, MM_SMEM);

    const int nt = (N + 63) / 64;

    // Stage A+B: content bi-LSTM per feature set (shared weights)
    for (int s = 0; s < 3; s++) {
        gemm_bias<<<dim3((3 * N + 63) / 64, 4), 256, GEMM_SMEM>>>(
            xs[s], Wih_c, bih_c, bhh_c, gxbuf, 3 * N);
        bilstm_mma<<<dim3(nt, 2, 1), 256, MM_SMEM>>>(
            gxbuf, nullptr, Whh_c, content + (size_t)s * N * DD, N, 3);
    }

    // Stage C: precompute neighbor gate pre-activations per source type
    for (int s = 0; s < 3; s++) {
        gemm_bias<<<dim3(nt, 4), 256, GEMM_SMEM>>>(
            content + (size_t)s * N * DD,
            Wih_n + (size_t)s * ROW * DD,
            bih_n + s * ROW, bhh_n + s * ROW,
            gxn + (size_t)s * N * ROW, N);
    }

    // Stage D: 9 neighbor bi-LSTM reductions on warp MMAs (split-bf16)
    bilstm_mma<<<dim3(nt, 2, 9), 256, MM_SMEM>>>(gxn, nbr, Whh_n, neigh, N, 10);

    // Stage E: attention fusion
    attn_fuse<<<(3 * N + 7) / 8, 256>>>(content, neigh, attn_w, attn_b, out, N);
}

// round 13
// speedup vs baseline: 1.8646x; 1.2673x over previous
#include <cuda_runtime.h>
#include <cuda_bf16.h>
#include <cstdint>

// Problem constants (fixed by the dataset): N=30000, C=3, D=128, K=10, H=64
#define DD   128
#define HH   64
#define GATE 256   // 4*H per direction
#define ROW  512   // both directions of gate pre-activations

#define NMAX 30000

// Scratch (static device globals — allocation-free rule)
__device__ __align__(16) float g_gxbuf[(size_t)NMAX * 3 * ROW];   // content gate preacts (reused per s)
__device__ __align__(16) float g_gxn[(size_t)3 * NMAX * ROW];     // neighbor gate preacts per s
__device__ __align__(16) float g_content[(size_t)3 * NMAX * DD];  // content embeddings
__device__ __align__(16) float g_neigh[(size_t)9 * NMAX * DD];    // neigh[d][s][n][128]

__device__ __forceinline__ float sigm(float x) { return __fdividef(1.f, 1.f + __expf(-x)); }
__device__ __forceinline__ float tanh_(float x) { return 2.f * __fdividef(1.f, 1.f + __expf(-2.f * x)) - 1.f; }

__device__ __forceinline__ uint32_t smem_u32(const void* p) {
    uint32_t a;
    asm("{ .reg .u64 t; cvta.to.shared.u64 t, %1; cvt.u32.u64 %0, t; }" : "=r"(a) : "l"(p));
    return a;
}

// warp-level bf16 MMA  D(16x8,f32) += A(16x16,bf16 row) * B(16x8,bf16 col)
__device__ __forceinline__ void mma16816(float& f0, float& f1, float& f2, float& f3,
                                         const uint32_t* a, const uint32_t* b) {
    asm volatile(
        "mma.sync.aligned.m16n8k16.row.col.f32.bf16.bf16.f32 "
        "{%0,%1,%2,%3}, {%4,%5,%6,%7}, {%8,%9}, {%0,%1,%2,%3};"
        : "+f"(f0), "+f"(f1), "+f"(f2), "+f"(f3)
        : "r"(a[0]), "r"(a[1]), "r"(a[2]), "r"(a[3]), "r"(b[0]), "r"(b[1]));
}
__device__ __forceinline__ void ldmx4(uint32_t* r, uint32_t addr) {
    asm volatile("ldmatrix.sync.aligned.m8n8.x4.shared.b16 {%0,%1,%2,%3}, [%4];"
        : "=r"(r[0]), "=r"(r[1]), "=r"(r[2]), "=r"(r[3]) : "r"(addr));
}

// ---------------------------------------------------------------------------
// GEMM: C[m][j] = sum_k A[m][k] * W[j][k] + b1[j] + b2[j]   (R8 version)
// ---------------------------------------------------------------------------
#define GEMM_SMEM ((128 * 68 + 128 * 132) * 4)

__global__ __launch_bounds__(256) void gemm_bias(
    const float* __restrict__ A, const float* __restrict__ W,
    const float* __restrict__ b1, const float* __restrict__ b2,
    float* __restrict__ C, int M)
{
    extern __shared__ float sm[];
    float* Ast = sm;              // [128 k][68 m]
    float* Wst = sm + 128 * 68;   // [128 k][132 j]
    const int tid = threadIdx.x;
    const int bm = blockIdx.x, jc = blockIdx.y;

    for (int q = tid; q < 64 * 32; q += 256) {
        int r = q >> 5;
        int k4 = (q & 31) << 2;
        int gm = bm * 64 + r;
        float4 v = make_float4(0.f, 0.f, 0.f, 0.f);
        if (gm < M) v = *(const float4*)(A + (size_t)gm * 128 + k4);
        Ast[(k4 + 0) * 68 + r] = v.x;
        Ast[(k4 + 1) * 68 + r] = v.y;
        Ast[(k4 + 2) * 68 + r] = v.z;
        Ast[(k4 + 3) * 68 + r] = v.w;
    }
    for (int q = tid; q < 128 * 32; q += 256) {
        int jj = q >> 5;
        int k4 = (q & 31) << 2;
        float4 v = *(const float4*)(W + ((size_t)(jc * 128 + jj)) * 128 + k4);
        Wst[(k4 + 0) * 132 + jj] = v.x;
        Wst[(k4 + 1) * 132 + jj] = v.y;
        Wst[(k4 + 2) * 132 + jj] = v.z;
        Wst[(k4 + 3) * 132 + jj] = v.w;
    }
    __syncthreads();

    const int tx = tid & 15;
    const int ty = tid >> 4;
    float acc[4][8];
#pragma unroll
    for (int i = 0; i < 4; i++)
#pragma unroll
        for (int j = 0; j < 8; j++) acc[i][j] = 0.f;

#pragma unroll 4
    for (int kk = 0; kk < 128; kk++) {
        float4 a  = *(const float4*)(Ast + kk * 68 + (ty << 2));
        float4 w0 = *(const float4*)(Wst + kk * 132 + (tx << 3));
        float4 w1 = *(const float4*)(Wst + kk * 132 + (tx << 3) + 4);
        float av[4] = {a.x, a.y, a.z, a.w};
        float wv[8] = {w0.x, w0.y, w0.z, w0.w, w1.x, w1.y, w1.z, w1.w};
#pragma unroll
        for (int mi = 0; mi < 4; mi++)
#pragma unroll
            for (int ji = 0; ji < 8; ji++) acc[mi][ji] += av[mi] * wv[ji];
    }

    const int jb = (jc << 7) + (tx << 3);
    float bb[8];
#pragma unroll
    for (int ji = 0; ji < 8; ji++) bb[ji] = b1[jb + ji] + b2[jb + ji];

#pragma unroll
    for (int mi = 0; mi < 4; mi++) {
        int gm = (bm << 6) + (ty << 2) + mi;
        if (gm < M) {
            float4 o0 = make_float4(acc[mi][0] + bb[0], acc[mi][1] + bb[1],
                                    acc[mi][2] + bb[2], acc[mi][3] + bb[3]);
            float4 o1 = make_float4(acc[mi][4] + bb[4], acc[mi][5] + bb[5],
                                    acc[mi][6] + bb[6], acc[mi][7] + bb[7]);
            *(float4*)(C + (size_t)gm * ROW + jb)     = o0;
            *(float4*)(C + (size_t)gm * ROW + jb + 4) = o1;
        }
    }
}

// ---------------------------------------------------------------------------
// Unified bi-LSTM recurrence on warp MMAs (split-bf16 hi/lo, fp32 accum).
// v3: 2 CTAs/SM.  Register diet vs v2:
//   - two-pass A fragments (16 live regs instead of 32)
//   - c / hsum state in padded SMEM (pitch 33 words -> conflict-free)
//   - __launch_bounds__(256, 2) caps regs at 128
//
// CTA = 64 nodes, one (s,d,dir), 256 threads (8 warps).
// Warp w owns hidden-unit band uw = w*8..w*8+7 across ALL 4 gates:
//   B frag for gate g covers cols j = g*64 + uw + (lane>>2).
// gx pre-activations load straight into the accumulators (C init).
// H (bf16 hi/lo) lives in double-buffered SMEM A tiles -> ONE barrier/step.
// ---------------------------------------------------------------------------
#define O_A   2560                 // after ids (64*10*4 max)
#define ABUF  9216                 // 64 rows * 144B (one hi or lo tile)
#define ASTEP 18432                // hi+lo pair
#define O_CS  (O_A + 2 * ASTEP)    // 39424: per-thread state [256][33] floats
#define MM_SMEM (O_CS + 256 * 33 * 4)   // 73216

__global__ __launch_bounds__(256, 2) void bilstm_mma(
    const float* __restrict__ gxn, const int* __restrict__ nbr,
    const float* __restrict__ WhhP, float* __restrict__ outP, int N, int K)
{
    extern __shared__ char smc[];
    int* ids = (int*)smc;
    const uint32_t sb = smem_u32(smc);

    const int tid = threadIdx.x;
    const int lane = tid & 31, w = tid >> 5;
    const int dir = blockIdx.y;

    // per-thread state in SMEM: cst[0..15] = cell c, cst[16..31] = hsum
    float* cst = (float*)(smc + O_CS) + tid * 33;

    const float* gx = gxn;
    const float* Whh = WhhP;
    float* out = outP;
    const int* idx = nbr;
    if (nbr) {
        int z = blockIdx.z;
        int s = z / 3, d = z - s * 3;
        gx  += (size_t)s * N * ROW;
        idx  = nbr + (size_t)(s * 3 + d) * N * K;
        Whh += (size_t)s * 2 * GATE * HH;
        out += (size_t)(d * 3 + s) * N * DD;
    }
    Whh += (size_t)dir * GATE * HH;
    const int node0 = blockIdx.x * 64;

    // Stage gather indices (neighbor mode only)
    if (nbr) {
        for (int i = tid; i < 64 * K; i += 256) {
            int m = i / K;
            int n = node0 + m;
            ids[i] = (n < N) ? idx[(size_t)n * K + (i - m * K)] : 0;
        }
    }
    // Zero A buffer 0 (hi+lo): H = 0
    for (int i = tid; i < ASTEP / 4; i += 256)
        ((float*)(smc + O_A))[i] = 0.f;
    // Zero per-thread state
#pragma unroll
    for (int i = 0; i < 32; i++) cst[i] = 0.f;

    // Persistent B fragments, gate-major permutation (split-bf16 from fp32 Whh).
    // frag reg0 = W[j][k0..k0+1], reg1 = W[j][k0+8..k0+9];
    //   j = g*64 + uw + (lane>>2), k0 = kt*16 + 2*(lane&3).
    const int uw = w << 3;
    uint32_t bh[4][4][2], bl[4][4][2];
    {
        const int jr = uw + (lane >> 2);
        const int kq = (lane & 3) << 1;
#pragma unroll
        for (int g = 0; g < 4; g++) {
            const float* wr = Whh + (size_t)(g * 64 + jr) * HH;
#pragma unroll
            for (int kt = 0; kt < 4; kt++) {
#pragma unroll
                for (int hb = 0; hb < 2; hb++) {
                    float2 x = *(const float2*)(wr + kt * 16 + kq + hb * 8);
                    __nv_bfloat16 hx = __float2bfloat16_rn(x.x);
                    __nv_bfloat16 hy = __float2bfloat16_rn(x.y);
                    __nv_bfloat16 lx = __float2bfloat16_rn(x.x - __bfloat162float(hx));
                    __nv_bfloat16 ly = __float2bfloat16_rn(x.y - __bfloat162float(hy));
                    bh[g][kt][hb] = ((uint32_t)__bfloat16_as_ushort(hy) << 16)
                                  | (uint32_t)__bfloat16_as_ushort(hx);
                    bl[g][kt][hb] = ((uint32_t)__bfloat16_as_ushort(ly) << 16)
                                  | (uint32_t)__bfloat16_as_ushort(lx);
                }
            }
        }
    }
    __syncthreads();

    // ldmatrix lane addressing for 16x16 A tiles (pitch 144B)
    const int gA = lane >> 3, rA = lane & 7;
    const int arow = ((gA & 1) << 3) + rA;
    const int acol = (gA >> 1) << 4;

    // Per-thread D ownership: rows mt*16 + rq (+8), u-pair (u, u+1)
    const int rq = lane >> 2;
    const int u = uw + ((lane & 3) << 1);

    const float* gbase = gx + dir * GATE + u;

    for (int t = 0; t < K; t++) {
        const int tt = dir ? (K - 1 - t) : t;
        const uint32_t rb = sb + O_A + (uint32_t)(t & 1) * ASTEP;         // read buf
        char* wbp = smc + O_A + ((t + 1) & 1) * ASTEP;                    // write buf

#pragma unroll
        for (int mt = 0; mt < 4; mt++) {
            const int m0 = (mt << 4) + rq, m1 = m0 + 8;
            size_t row0, row1;
            if (nbr) {
                row0 = (size_t)ids[m0 * K + tt];
                row1 = (size_t)ids[m1 * K + tt];
            } else {
                int n0 = node0 + m0, n1 = node0 + m1;
                row0 = (size_t)(n0 < N ? n0 : N - 1) * K + tt;
                row1 = (size_t)(n1 < N ? n1 : N - 1) * K + tt;
            }
            const float* p0 = gbase + row0 * ROW;
            const float* p1 = gbase + row1 * ROW;

            const uint32_t ab = rb + (uint32_t)((mt << 4) + arow) * 144 + acol;

            // Accumulators init from gx
            float fg[4][4];
#pragma unroll
            for (int g = 0; g < 4; g++) {
                float2 v0 = *(const float2*)(p0 + (g << 6));
                float2 v1 = *(const float2*)(p1 + (g << 6));
                fg[g][0] = v0.x; fg[g][1] = v0.y; fg[g][2] = v1.x; fg[g][3] = v1.y;
            }

            // Pass 1: A = Hhi  -> terms Hhi@Whi + Hhi@Wlo
            uint32_t af[4][4];
#pragma unroll
            for (int kt = 0; kt < 4; kt++) ldmx4(af[kt], ab + kt * 32);
#pragma unroll
            for (int g = 0; g < 4; g++)
#pragma unroll
                for (int kt = 0; kt < 4; kt++) {
                    mma16816(fg[g][0], fg[g][1], fg[g][2], fg[g][3], af[kt], bh[g][kt]);
                    mma16816(fg[g][0], fg[g][1], fg[g][2], fg[g][3], af[kt], bl[g][kt]);
                }

            // Pass 2: A = Hlo (reuse regs) -> term Hlo@Whi
#pragma unroll
            for (int kt = 0; kt < 4; kt++) ldmx4(af[kt], ab + ABUF + kt * 32);
#pragma unroll
            for (int g = 0; g < 4; g++)
#pragma unroll
                for (int kt = 0; kt < 4; kt++)
                    mma16816(fg[g][0], fg[g][1], fg[g][2], fg[g][3], af[kt], bh[g][kt]);

            // Gate math; c/hsum state in SMEM; write new H (bf16 hi/lo)
            unsigned short hh[4], hl[4];
#pragma unroll
            for (int pos = 0; pos < 4; pos++) {
                float cc = cst[mt * 4 + pos];
                cc = sigm(fg[1][pos]) * cc + sigm(fg[0][pos]) * tanh_(fg[2][pos]);
                cst[mt * 4 + pos] = cc;
                float h = sigm(fg[3][pos]) * tanh_(cc);
                cst[16 + mt * 4 + pos] += h;
                __nv_bfloat16 hb16 = __float2bfloat16_rn(h);
                __nv_bfloat16 lb16 = __float2bfloat16_rn(h - __bfloat162float(hb16));
                hh[pos] = __bfloat16_as_ushort(hb16);
                hl[pos] = __bfloat16_as_ushort(lb16);
            }
            // rows m0 (pos 0,1) and m1 (pos 2,3), u-pair at byte offset u*2
            *(uint32_t*)(wbp + m0 * 144 + u * 2) =
                (uint32_t)hh[0] | ((uint32_t)hh[1] << 16);
            *(uint32_t*)(wbp + ABUF + m0 * 144 + u * 2) =
                (uint32_t)hl[0] | ((uint32_t)hl[1] << 16);
            *(uint32_t*)(wbp + m1 * 144 + u * 2) =
                (uint32_t)hh[2] | ((uint32_t)hh[3] << 16);
            *(uint32_t*)(wbp + ABUF + m1 * 144 + u * 2) =
                (uint32_t)hl[2] | ((uint32_t)hl[3] << 16);
        }
        __syncthreads();   // next buffer complete; prior buffer reads all done
    }

    // Output: mean over K steps (hsum lives in cst[16..31])
    const float inv = 1.f / (float)K;
#pragma unroll
    for (int mt = 0; mt < 4; mt++) {
        const int n0 = node0 + (mt << 4) + rq;
        const int n1 = n0 + 8;
        if (n0 < N)
            *(float2*)(out + (size_t)n0 * DD + dir * HH + u) =
                make_float2(cst[16 + mt * 4 + 0] * inv, cst[16 + mt * 4 + 1] * inv);
        if (n1 < N)
            *(float2*)(out + (size_t)n1 * DD + dir * HH + u) =
                make_float2(cst[16 + mt * 4 + 2] * inv, cst[16 + mt * 4 + 3] * inv);
    }
}

// ---------------------------------------------------------------------------
// Attention fusion: one warp per (d, n).
// ---------------------------------------------------------------------------
__global__ void attn_fuse(const float* __restrict__ content,
                          const float* __restrict__ neigh,
                          const float* __restrict__ attn_w,
                          const float* __restrict__ attn_b,
                          float* __restrict__ out, int N)
{
    int w = (blockIdx.x * blockDim.x + threadIdx.x) >> 5;
    if (w >= 3 * N) return;
    int lane = threadIdx.x & 31;
    int d = w / N, n = w - d * N;

    const float* dh = content + ((size_t)d * N + n) * DD;
    const float* aw = attn_w + d * 256;
    float4 w1 = *(const float4*)(aw + lane * 4);
    float4 w2 = *(const float4*)(aw + 128 + lane * 4);

    float4 s[4];
#pragma unroll
    for (int i = 0; i < 3; i++)
        s[i] = *(const float4*)(neigh + (((size_t)(d * 3 + i)) * N + n) * DD + lane * 4);
    s[3] = *(const float4*)(dh + lane * 4);

    float base = s[3].x * w1.x + s[3].y * w1.y + s[3].z * w1.z + s[3].w * w1.w;
    float l[4];
#pragma unroll
    for (int i = 0; i < 4; i++)
        l[i] = s[i].x * w2.x + s[i].y * w2.y + s[i].z * w2.z + s[i].w * w2.w;

#pragma unroll
    for (int off = 16; off; off >>= 1) {
        base += __shfl_xor_sync(0xffffffffu, base, off);
#pragma unroll
        for (int i = 0; i < 4; i++) l[i] += __shfl_xor_sync(0xffffffffu, l[i], off);
    }

    float b = attn_b[d];
    float mx = -1e30f;
#pragma unroll
    for (int i = 0; i < 4; i++) {
        float v = base + l[i] + b;
        l[i] = v > 0.f ? v : 0.01f * v;
        mx = fmaxf(mx, l[i]);
    }
    float se = 0.f;
#pragma unroll
    for (int i = 0; i < 4; i++) { l[i] = __expf(l[i] - mx); se += l[i]; }
    float inv = 1.f / se;

    float4 o = make_float4(0.f, 0.f, 0.f, 0.f);
#pragma unroll
    for (int i = 0; i < 4; i++) {
        float wi = l[i] * inv;
        o.x += wi * s[i].x; o.y += wi * s[i].y; o.z += wi * s[i].z; o.w += wi * s[i].w;
    }
    *(float4*)(out + ((size_t)d * N + n) * DD + lane * 4) = o;
}

// ---------------------------------------------------------------------------
extern "C" void kernel_launch(void* const* d_in, const int* in_sizes, int n_in,
                              void* d_out, int out_size)
{
    const float* xs[3]   = {(const float*)d_in[0], (const float*)d_in[1], (const float*)d_in[2]};
    const float* Wih_c   = (const float*)d_in[3];
    const float* Whh_c   = (const float*)d_in[4];
    const float* bih_c   = (const float*)d_in[5];
    const float* bhh_c   = (const float*)d_in[6];
    const float* Wih_n   = (const float*)d_in[7];
    const float* Whh_n   = (const float*)d_in[8];
    const float* bih_n   = (const float*)d_in[9];
    const float* bhh_n   = (const float*)d_in[10];
    const float* attn_w  = (const float*)d_in[11];
    const float* attn_b  = (const float*)d_in[12];
    const int*   nbr     = (const int*)d_in[13];
    float* out = (float*)d_out;

    const int N = in_sizes[0] / (3 * DD);   // 30000

    float *gxbuf, *gxn, *content, *neigh;
    cudaGetSymbolAddress((void**)&gxbuf,   g_gxbuf);
    cudaGetSymbolAddress((void**)&gxn,     g_gxn);
    cudaGetSymbolAddress((void**)&content, g_content);
    cudaGetSymbolAddress((void**)&neigh,   g_neigh);

    cudaFuncSetAttribute(gemm_bias,  cudaFuncAttributeMaxDynamicSharedMemorySize, GEMM_SMEM);
    cudaFuncSetAttribute(bilstm_mma, cudaFuncAttributeMaxDynamicSharedMemorySize, MM_SMEM);

    const int nt = (N + 63) / 64;

    // Stage A+B: content bi-LSTM per feature set (shared weights)
    for (int s = 0; s < 3; s++) {
        gemm_bias<<<dim3((3 * N + 63) / 64, 4), 256, GEMM_SMEM>>>(
            xs[s], Wih_c, bih_c, bhh_c, gxbuf, 3 * N);
        bilstm_mma<<<dim3(nt, 2, 1), 256, MM_SMEM>>>(
            gxbuf, nullptr, Whh_c, content + (size_t)s * N * DD, N, 3);
    }

    // Stage C: precompute neighbor gate pre-activations per source type
    for (int s = 0; s < 3; s++) {
        gemm_bias<<<dim3(nt, 4), 256, GEMM_SMEM>>>(
            content + (size_t)s * N * DD,
            Wih_n + (size_t)s * ROW * DD,
            bih_n + s * ROW, bhh_n + s * ROW,
            gxn + (size_t)s * N * ROW, N);
    }

    // Stage D: 9 neighbor bi-LSTM reductions on warp MMAs (split-bf16)
    bilstm_mma<<<dim3(nt, 2, 9), 256, MM_SMEM>>>(gxn, nbr, Whh_n, neigh, N, 10);

    // Stage E: attention fusion
    attn_fuse<<<(3 * N + 7) / 8, 256>>>(content, neigh, attn_w, attn_b, out, N);
}

// round 14
// speedup vs baseline: 2.6099x; 1.3997x over previous
#include <cuda_runtime.h>
#include <cuda_bf16.h>
#include <cstdint>

// Problem constants (fixed by the dataset): N=30000, C=3, D=128, K=10, H=64
#define DD   128
#define HH   64
#define GATE 256   // 4*H per direction
#define ROW  512   // both directions of gate pre-activations

#define NMAX 30000

// Scratch (static device globals — allocation-free rule)
__device__ __align__(16) float g_gxbuf[(size_t)NMAX * 3 * ROW];   // content gate preacts (reused per s)
__device__ __align__(16) float g_gxn[(size_t)3 * NMAX * ROW];     // neighbor gate preacts per s
__device__ __align__(16) float g_content[(size_t)3 * NMAX * DD];  // content embeddings
__device__ __align__(16) float g_neigh[(size_t)9 * NMAX * DD];    // neigh[d][s][n][128]

// Fragment-native split-bf16 input weights + fused biases (4 sets: Wih_c, Wih_n[0..2])
// Layout per set: index ((nb*8+kt)*32+lane)*32 + {nt*2+r (hi), 16+nt*2+r (lo)}
__device__ __align__(16) uint32_t g_bp[4][65536];
__device__ float g_bsum[4][512];

__device__ __forceinline__ float sigm(float x) { return __fdividef(1.f, 1.f + __expf(-x)); }
__device__ __forceinline__ float tanh_(float x) { return 2.f * __fdividef(1.f, 1.f + __expf(-2.f * x)) - 1.f; }

__device__ __forceinline__ uint32_t smem_u32(const void* p) {
    uint32_t a;
    asm("{ .reg .u64 t; cvta.to.shared.u64 t, %1; cvt.u32.u64 %0, t; }" : "=r"(a) : "l"(p));
    return a;
}

// warp-level bf16 MMA  D(16x8,f32) += A(16x16,bf16 row) * B(16x8,bf16 col)
__device__ __forceinline__ void mma16816(float& f0, float& f1, float& f2, float& f3,
                                         const uint32_t* a, const uint32_t* b) {
    asm volatile(
        "mma.sync.aligned.m16n8k16.row.col.f32.bf16.bf16.f32 "
        "{%0,%1,%2,%3}, {%4,%5,%6,%7}, {%8,%9}, {%0,%1,%2,%3};"
        : "+f"(f0), "+f"(f1), "+f"(f2), "+f"(f3)
        : "r"(a[0]), "r"(a[1]), "r"(a[2]), "r"(a[3]), "r"(b[0]), "r"(b[1]));
}
__device__ __forceinline__ void ldmx4(uint32_t* r, uint32_t addr) {
    asm volatile("ldmatrix.sync.aligned.m8n8.x4.shared.b16 {%0,%1,%2,%3}, [%4];"
        : "=r"(r[0]), "=r"(r[1]), "=r"(r[2]), "=r"(r[3]) : "r"(addr));
}

__device__ __forceinline__ uint32_t pack_hi(float x, float y, float& rx, float& ry) {
    __nv_bfloat16 hx = __float2bfloat16_rn(x);
    __nv_bfloat16 hy = __float2bfloat16_rn(y);
    rx = x - __bfloat162float(hx);
    ry = y - __bfloat162float(hy);
    return ((uint32_t)__bfloat16_as_ushort(hy) << 16) | (uint32_t)__bfloat16_as_ushort(hx);
}
__device__ __forceinline__ uint32_t pack_bf(float x, float y) {
    return ((uint32_t)__bfloat16_as_ushort(__float2bfloat16_rn(y)) << 16)
         | (uint32_t)__bfloat16_as_ushort(__float2bfloat16_rn(x));
}

// ---------------------------------------------------------------------------
// Weight prep: convert the 4 input-projection weight sets [512][128] fp32 to
// fragment-native split-bf16, and fuse biases.  blockIdx.x = set (0..3).
// Per-lane frag element: j = nb*64 + nt*8 + (lane>>2), k = kt*16 + 2(lane&3) + 8r.
// ---------------------------------------------------------------------------
__global__ void prep_weights(const float* __restrict__ Wc,
                             const float* __restrict__ b1c, const float* __restrict__ b2c,
                             const float* __restrict__ Wn,
                             const float* __restrict__ b1n, const float* __restrict__ b2n)
{
    const int set = blockIdx.x;
    const float* W  = (set == 0) ? Wc : (Wn + (size_t)(set - 1) * 512 * 128);
    const float* b1 = (set == 0) ? b1c : (b1n + (size_t)(set - 1) * 512);
    const float* b2 = (set == 0) ? b2c : (b2n + (size_t)(set - 1) * 512);

    for (int i = threadIdx.x; i < 32768; i += blockDim.x) {
        int r    = i & 1;
        int nt   = (i >> 1) & 7;
        int lane = (i >> 4) & 31;
        int kt   = (i >> 9) & 7;
        int nb   = (i >> 12) & 7;
        int j = nb * 64 + nt * 8 + (lane >> 2);
        int k = kt * 16 + ((lane & 3) << 1) + r * 8;
        float w0 = W[(size_t)j * 128 + k];
        float w1 = W[(size_t)j * 128 + k + 1];
        float l0, l1;
        uint32_t hi = pack_hi(w0, w1, l0, l1);
        uint32_t lo = pack_bf(l0, l1);
        uint32_t base = (uint32_t)((nb * 8 + kt) * 32 + lane) * 32;
        g_bp[set][base + nt * 2 + r]      = hi;
        g_bp[set][base + 16 + nt * 2 + r] = lo;
    }
    for (int j = threadIdx.x; j < 512; j += blockDim.x)
        g_bsum[set][j] = b1[j] + b2[j];
}

// ---------------------------------------------------------------------------
// Tensor-core GEMM: C[m][j] = sum_k A[m][k]*W[j][k] + bsum[j]
// A [M][128] fp32; W pre-packed (g_bp set); C [M][512].
// CTA: 64 rows x 512 cols, 256 threads (8 warps, warp = 64-col band).
// A converted to split-bf16 hi/lo SMEM tiles (pitch 272B, conflict-free ldsm).
// 3-term split-bf16 MMA, fp32 accum, bias-initialized accumulators.
// ---------------------------------------------------------------------------
#define APITCH 272
#define ATILE  (64 * APITCH)          // 17408 bytes per (hi|lo) tile
#define GT_SMEM (2 * ATILE)           // 34816

__global__ __launch_bounds__(256, 2) void gemm_tc(
    const float* __restrict__ A, const uint32_t* __restrict__ Bp,
    const float* __restrict__ bsum, float* __restrict__ C, int M)
{
    extern __shared__ char smc[];
    const uint32_t sb = smem_u32(smc);
    const int tid = threadIdx.x;
    const int lane = tid & 31, w = tid >> 5;
    const int row0 = blockIdx.x * 64;

    // Load A rows, convert to split-bf16 hi/lo tiles
    for (int q = tid; q < 64 * 32; q += 256) {
        int r = q >> 5;
        int kc = (q & 31) << 2;       // k chunk of 4
        int gm = row0 + r;
        float4 v = make_float4(0.f, 0.f, 0.f, 0.f);
        if (gm < M) v = *(const float4*)(A + (size_t)gm * 128 + kc);
        float lx, ly, lz, lw;
        uint32_t h01 = pack_hi(v.x, v.y, lx, ly);
        uint32_t h23 = pack_hi(v.z, v.w, lz, lw);
        uint32_t l01 = pack_bf(lx, ly);
        uint32_t l23 = pack_bf(lz, lw);
        char* pr = smc + r * APITCH + kc * 2;
        *(uint2*)(pr)         = make_uint2(h01, h23);
        *(uint2*)(pr + ATILE) = make_uint2(l01, l23);
    }
    __syncthreads();

    // Bias registers (f0,f1 -> cols c0,c0+1; f2,f3 same cols, row+8)
    const int cq = (lane & 3) << 1;
    const int rq = lane >> 2;
    float2 bv[8];
#pragma unroll
    for (int nt = 0; nt < 8; nt++)
        bv[nt] = *(const float2*)(bsum + w * 64 + nt * 8 + cq);

    // ldmatrix lane addressing (validated mapping, pitch 272)
    const int gA = lane >> 3, rA = lane & 7;
    const int arow = ((gA & 1) << 3) + rA;
    const int acol = (gA >> 1) << 4;
    const uint32_t abase0 = sb + (uint32_t)arow * APITCH + acol;

    const uint32_t* bpw = Bp + (uint32_t)w * (8 * 32 * 32);

#pragma unroll
    for (int mt = 0; mt < 4; mt++) {
        float acc[8][4];
#pragma unroll
        for (int nt = 0; nt < 8; nt++) {
            acc[nt][0] = bv[nt].x; acc[nt][1] = bv[nt].y;
            acc[nt][2] = bv[nt].x; acc[nt][3] = bv[nt].y;
        }

#pragma unroll
        for (int kt = 0; kt < 8; kt++) {
            // B fragments: 32 uints (16 hi + 16 lo), 8 coalesced LDG.128
            uint32_t bfr[32];
            const uint32_t* bp = bpw + (uint32_t)(kt * 32 + lane) * 32;
#pragma unroll
            for (int q = 0; q < 8; q++)
                *(uint4*)&bfr[q * 4] = *(const uint4*)(bp + q * 4);

            const uint32_t ab = abase0 + (uint32_t)(mt * 16) * APITCH + kt * 32;
            uint32_t af[4];
            // Pass 1: A = hi  -> Ahi@Whi + Ahi@Wlo
            ldmx4(af, ab);
#pragma unroll
            for (int nt = 0; nt < 8; nt++) {
                mma16816(acc[nt][0], acc[nt][1], acc[nt][2], acc[nt][3], af, &bfr[nt * 2]);
                mma16816(acc[nt][0], acc[nt][1], acc[nt][2], acc[nt][3], af, &bfr[16 + nt * 2]);
            }
            // Pass 2: A = lo  -> Alo@Whi
            ldmx4(af, ab + ATILE);
#pragma unroll
            for (int nt = 0; nt < 8; nt++)
                mma16816(acc[nt][0], acc[nt][1], acc[nt][2], acc[nt][3], af, &bfr[nt * 2]);
        }

        // Epilogue: write C (two 8B stores per nt)
        const int m0 = row0 + mt * 16 + rq;
        const int m1 = m0 + 8;
#pragma unroll
        for (int nt = 0; nt < 8; nt++) {
            const int c0 = w * 64 + nt * 8 + cq;
            if (m0 < M)
                *(float2*)(C + (size_t)m0 * ROW + c0) = make_float2(acc[nt][0], acc[nt][1]);
            if (m1 < M)
                *(float2*)(C + (size_t)m1 * ROW + c0) = make_float2(acc[nt][2], acc[nt][3]);
        }
    }
}

// ---------------------------------------------------------------------------
// Unified bi-LSTM recurrence on warp MMAs (split-bf16 hi/lo, fp32 accum).
// R13 version (2 CTAs/SM): two-pass A fragments, c/hsum state in padded SMEM.
// ---------------------------------------------------------------------------
#define O_A   2560                 // after ids (64*10*4 max)
#define ABUF  9216                 // 64 rows * 144B (one hi or lo tile)
#define ASTEP 18432                // hi+lo pair
#define O_CS  (O_A + 2 * ASTEP)    // per-thread state [256][33] floats
#define MM_SMEM (O_CS + 256 * 33 * 4)   // 73216

__global__ __launch_bounds__(256, 2) void bilstm_mma(
    const float* __restrict__ gxn, const int* __restrict__ nbr,
    const float* __restrict__ WhhP, float* __restrict__ outP, int N, int K)
{
    extern __shared__ char smc[];
    int* ids = (int*)smc;
    const uint32_t sb = smem_u32(smc);

    const int tid = threadIdx.x;
    const int lane = tid & 31, w = tid >> 5;
    const int dir = blockIdx.y;

    float* cst = (float*)(smc + O_CS) + tid * 33;

    const float* gx = gxn;
    const float* Whh = WhhP;
    float* out = outP;
    const int* idx = nbr;
    if (nbr) {
        int z = blockIdx.z;
        int s = z / 3, d = z - s * 3;
        gx  += (size_t)s * N * ROW;
        idx  = nbr + (size_t)(s * 3 + d) * N * K;
        Whh += (size_t)s * 2 * GATE * HH;
        out += (size_t)(d * 3 + s) * N * DD;
    }
    Whh += (size_t)dir * GATE * HH;
    const int node0 = blockIdx.x * 64;

    if (nbr) {
        for (int i = tid; i < 64 * K; i += 256) {
            int m = i / K;
            int n = node0 + m;
            ids[i] = (n < N) ? idx[(size_t)n * K + (i - m * K)] : 0;
        }
    }
    for (int i = tid; i < ASTEP / 4; i += 256)
        ((float*)(smc + O_A))[i] = 0.f;
#pragma unroll
    for (int i = 0; i < 32; i++) cst[i] = 0.f;

    // Persistent B fragments, gate-major permutation (split-bf16 from fp32 Whh)
    const int uw = w << 3;
    uint32_t bh[4][4][2], bl[4][4][2];
    {
        const int jr = uw + (lane >> 2);
        const int kq = (lane & 3) << 1;
#pragma unroll
        for (int g = 0; g < 4; g++) {
            const float* wr = Whh + (size_t)(g * 64 + jr) * HH;
#pragma unroll
            for (int kt = 0; kt < 4; kt++) {
#pragma unroll
                for (int hb = 0; hb < 2; hb++) {
                    float2 x = *(const float2*)(wr + kt * 16 + kq + hb * 8);
                    float lx, ly;
                    bh[g][kt][hb] = pack_hi(x.x, x.y, lx, ly);
                    bl[g][kt][hb] = pack_bf(lx, ly);
                }
            }
        }
    }
    __syncthreads();

    const int gA = lane >> 3, rA = lane & 7;
    const int arow = ((gA & 1) << 3) + rA;
    const int acol = (gA >> 1) << 4;

    const int rq = lane >> 2;
    const int u = uw + ((lane & 3) << 1);

    const float* gbase = gx + dir * GATE + u;

    for (int t = 0; t < K; t++) {
        const int tt = dir ? (K - 1 - t) : t;
        const uint32_t rb = sb + O_A + (uint32_t)(t & 1) * ASTEP;
        char* wbp = smc + O_A + ((t + 1) & 1) * ASTEP;

#pragma unroll
        for (int mt = 0; mt < 4; mt++) {
            const int m0 = (mt << 4) + rq, m1 = m0 + 8;
            size_t row0, row1;
            if (nbr) {
                row0 = (size_t)ids[m0 * K + tt];
                row1 = (size_t)ids[m1 * K + tt];
            } else {
                int n0 = node0 + m0, n1 = node0 + m1;
                row0 = (size_t)(n0 < N ? n0 : N - 1) * K + tt;
                row1 = (size_t)(n1 < N ? n1 : N - 1) * K + tt;
            }
            const float* p0 = gbase + row0 * ROW;
            const float* p1 = gbase + row1 * ROW;

            const uint32_t ab = rb + (uint32_t)((mt << 4) + arow) * 144 + acol;

            float fg[4][4];
#pragma unroll
            for (int g = 0; g < 4; g++) {
                float2 v0 = *(const float2*)(p0 + (g << 6));
                float2 v1 = *(const float2*)(p1 + (g << 6));
                fg[g][0] = v0.x; fg[g][1] = v0.y; fg[g][2] = v1.x; fg[g][3] = v1.y;
            }

            uint32_t af[4][4];
#pragma unroll
            for (int kt = 0; kt < 4; kt++) ldmx4(af[kt], ab + kt * 32);
#pragma unroll
            for (int g = 0; g < 4; g++)
#pragma unroll
                for (int kt = 0; kt < 4; kt++) {
                    mma16816(fg[g][0], fg[g][1], fg[g][2], fg[g][3], af[kt], bh[g][kt]);
                    mma16816(fg[g][0], fg[g][1], fg[g][2], fg[g][3], af[kt], bl[g][kt]);
                }

#pragma unroll
            for (int kt = 0; kt < 4; kt++) ldmx4(af[kt], ab + ABUF + kt * 32);
#pragma unroll
            for (int g = 0; g < 4; g++)
#pragma unroll
                for (int kt = 0; kt < 4; kt++)
                    mma16816(fg[g][0], fg[g][1], fg[g][2], fg[g][3], af[kt], bh[g][kt]);

            unsigned short hh[4], hl[4];
#pragma unroll
            for (int pos = 0; pos < 4; pos++) {
                float cc = cst[mt * 4 + pos];
                cc = sigm(fg[1][pos]) * cc + sigm(fg[0][pos]) * tanh_(fg[2][pos]);
                cst[mt * 4 + pos] = cc;
                float h = sigm(fg[3][pos]) * tanh_(cc);
                cst[16 + mt * 4 + pos] += h;
                __nv_bfloat16 hb16 = __float2bfloat16_rn(h);
                __nv_bfloat16 lb16 = __float2bfloat16_rn(h - __bfloat162float(hb16));
                hh[pos] = __bfloat16_as_ushort(hb16);
                hl[pos] = __bfloat16_as_ushort(lb16);
            }
            *(uint32_t*)(wbp + m0 * 144 + u * 2) =
                (uint32_t)hh[0] | ((uint32_t)hh[1] << 16);
            *(uint32_t*)(wbp + ABUF + m0 * 144 + u * 2) =
                (uint32_t)hl[0] | ((uint32_t)hl[1] << 16);
            *(uint32_t*)(wbp + m1 * 144 + u * 2) =
                (uint32_t)hh[2] | ((uint32_t)hh[3] << 16);
            *(uint32_t*)(wbp + ABUF + m1 * 144 + u * 2) =
                (uint32_t)hl[2] | ((uint32_t)hl[3] << 16);
        }
        __syncthreads();
    }

    const float inv = 1.f / (float)K;
#pragma unroll
    for (int mt = 0; mt < 4; mt++) {
        const int n0 = node0 + (mt << 4) + rq;
        const int n1 = n0 + 8;
        if (n0 < N)
            *(float2*)(out + (size_t)n0 * DD + dir * HH + u) =
                make_float2(cst[16 + mt * 4 + 0] * inv, cst[16 + mt * 4 + 1] * inv);
        if (n1 < N)
            *(float2*)(out + (size_t)n1 * DD + dir * HH + u) =
                make_float2(cst[16 + mt * 4 + 2] * inv, cst[16 + mt * 4 + 3] * inv);
    }
}

// ---------------------------------------------------------------------------
// Attention fusion: one warp per (d, n).
// ---------------------------------------------------------------------------
__global__ void attn_fuse(const float* __restrict__ content,
                          const float* __restrict__ neigh,
                          const float* __restrict__ attn_w,
                          const float* __restrict__ attn_b,
                          float* __restrict__ out, int N)
{
    int w = (blockIdx.x * blockDim.x + threadIdx.x) >> 5;
    if (w >= 3 * N) return;
    int lane = threadIdx.x & 31;
    int d = w / N, n = w - d * N;

    const float* dh = content + ((size_t)d * N + n) * DD;
    const float* aw = attn_w + d * 256;
    float4 w1 = *(const float4*)(aw + lane * 4);
    float4 w2 = *(const float4*)(aw + 128 + lane * 4);

    float4 s[4];
#pragma unroll
    for (int i = 0; i < 3; i++)
        s[i] = *(const float4*)(neigh + (((size_t)(d * 3 + i)) * N + n) * DD + lane * 4);
    s[3] = *(const float4*)(dh + lane * 4);

    float base = s[3].x * w1.x + s[3].y * w1.y + s[3].z * w1.z + s[3].w * w1.w;
    float l[4];
#pragma unroll
    for (int i = 0; i < 4; i++)
        l[i] = s[i].x * w2.x + s[i].y * w2.y + s[i].z * w2.z + s[i].w * w2.w;

#pragma unroll
    for (int off = 16; off; off >>= 1) {
        base += __shfl_xor_sync(0xffffffffu, base, off);
#pragma unroll
        for (int i = 0; i < 4; i++) l[i] += __shfl_xor_sync(0xffffffffu, l[i], off);
    }

    float b = attn_b[d];
    float mx = -1e30f;
#pragma unroll
    for (int i = 0; i < 4; i++) {
        float v = base + l[i] + b;
        l[i] = v > 0.f ? v : 0.01f * v;
        mx = fmaxf(mx, l[i]);
    }
    float se = 0.f;
#pragma unroll
    for (int i = 0; i < 4; i++) { l[i] = __expf(l[i] - mx); se += l[i]; }
    float inv = 1.f / se;

    float4 o = make_float4(0.f, 0.f, 0.f, 0.f);
#pragma unroll
    for (int i = 0; i < 4; i++) {
        float wi = l[i] * inv;
        o.x += wi * s[i].x; o.y += wi * s[i].y; o.z += wi * s[i].z; o.w += wi * s[i].w;
    }
    *(float4*)(out + ((size_t)d * N + n) * DD + lane * 4) = o;
}

// ---------------------------------------------------------------------------
extern "C" void kernel_launch(void* const* d_in, const int* in_sizes, int n_in,
                              void* d_out, int out_size)
{
    const float* xs[3]   = {(const float*)d_in[0], (const float*)d_in[1], (const float*)d_in[2]};
    const float* Wih_c   = (const float*)d_in[3];
    const float* Whh_c   = (const float*)d_in[4];
    const float* bih_c   = (const float*)d_in[5];
    const float* bhh_c   = (const float*)d_in[6];
    const float* Wih_n   = (const float*)d_in[7];
    const float* Whh_n   = (const float*)d_in[8];
    const float* bih_n   = (const float*)d_in[9];
    const float* bhh_n   = (const float*)d_in[10];
    const float* attn_w  = (const float*)d_in[11];
    const float* attn_b  = (const float*)d_in[12];
    const int*   nbr     = (const int*)d_in[13];
    float* out = (float*)d_out;

    const int N = in_sizes[0] / (3 * DD);   // 30000

    float *gxbuf, *gxn, *content, *neigh, *bsum;
    uint32_t* bp;
    cudaGetSymbolAddress((void**)&gxbuf,   g_gxbuf);
    cudaGetSymbolAddress((void**)&gxn,     g_gxn);
    cudaGetSymbolAddress((void**)&content, g_content);
    cudaGetSymbolAddress((void**)&neigh,   g_neigh);
    cudaGetSymbolAddress((void**)&bp,      g_bp);
    cudaGetSymbolAddress((void**)&bsum,    g_bsum);

    cudaFuncSetAttribute(gemm_tc,    cudaFuncAttributeMaxDynamicSharedMemorySize, GT_SMEM);
    cudaFuncSetAttribute(bilstm_mma, cudaFuncAttributeMaxDynamicSharedMemorySize, MM_SMEM);

    const int nt = (N + 63) / 64;

    // Stage 0: pack input-projection weights into fragment-native split-bf16
    prep_weights<<<4, 256>>>(Wih_c, bih_c, bhh_c, Wih_n, bih_n, bhh_n);

    // Stage A+B: content bi-LSTM per feature set (shared weights, set 0)
    for (int s = 0; s < 3; s++) {
        gemm_tc<<<(3 * N + 63) / 64, 256, GT_SMEM>>>(
            xs[s], bp, bsum, gxbuf, 3 * N);
        bilstm_mma<<<dim3(nt, 2, 1), 256, MM_SMEM>>>(
            gxbuf, nullptr, Whh_c, content + (size_t)s * N * DD, N, 3);
    }

    // Stage C: neighbor gate pre-activations per source type (sets 1..3)
    for (int s = 0; s < 3; s++) {
        gemm_tc<<<nt, 256, GT_SMEM>>>(
            content + (size_t)s * N * DD,
            bp + (size_t)(s + 1) * 65536,
            bsum + (size_t)(s + 1) * 512,
            gxn + (size_t)s * N * ROW, N);
    }

    // Stage D: 9 neighbor bi-LSTM reductions on warp MMAs (split-bf16)
    bilstm_mma<<<dim3(nt, 2, 9), 256, MM_SMEM>>>(gxn, nbr, Whh_n, neigh, N, 10);

    // Stage E: attention fusion
    attn_fuse<<<(3 * N + 7) / 8, 256>>>(content, neigh, attn_w, attn_b, out, N);
}